// round 14
// baseline (speedup 1.0000x reference)
#include <cuda_runtime.h>
#include <cuda_bf16.h>
#include <cstdint>

typedef unsigned long long u64;
typedef unsigned int u32;

// ---------------- scratch (device globals; no allocations allowed) ----------
__device__ unsigned short g_b1h[(size_t)64*128*128*32];  // enc1 out NHWC bf16
__device__ unsigned short g_b2h[(size_t)64*64*64*64];    // enc2 out NHWC bf16
__device__ unsigned short g_qh[(size_t)64*64*64*16];     // quantized NHWC bf16
__device__ unsigned short g_d1h[(size_t)64*128*128*64];  // dec1 out NHWC bf16
__device__ unsigned short g_d2h[(size_t)64*256*256*32];  // dec2 out NHWC bf16

__device__ u32   g_wfrag1[512];     // enc1 w  B-frags
__device__ u32   g_wfrag2[18432];   // enc2 w  B-frags
__device__ u32   g_wfragd1[4608];   // dec1 w  B-frags
__device__ u32   g_wfrag[9216];     // dec2 w  B-frags
__device__ u32   g_wfragd3[1152];   // dec3 w  B-frags (flip baked)
__device__ u32   g_wfragw3[512];    // enc3(1x1) w B-frags
__device__ u32   g_wfragcb[4096];   // codebook B-frags
__device__ float g_nrm[512];        // 0.5*||e_k||^2 (fp32)
__device__ double g_acc[2];         // [0]=vq sq-sum, [1]=recon sq-sum

// ---------------- helpers ----------------------------------------------------
__device__ __forceinline__ u32 bfpack(float lo, float hi){
  u32 r; asm("cvt.rn.bf16x2.f32 %0, %1, %2;" : "=r"(r) : "f"(hi), "f"(lo));
  return r;
}
__device__ __forceinline__ u32 smem_u32(const void* p){
  u32 a; asm("{ .reg .u64 t; cvta.to.shared.u64 t, %1; cvt.u32.u64 %0, t; }"
             : "=r"(a) : "l"(p));
  return a;
}
__device__ __forceinline__ float blockReduceSum(float v){
  __shared__ float red[32];
  #pragma unroll
  for (int o=16;o;o>>=1) v += __shfl_down_sync(0xffffffffu, v, o);
  int lane = threadIdx.x & 31, w = threadIdx.x >> 5;
  if (lane==0) red[w]=v;
  __syncthreads();
  if (w==0){
    v = (lane < ((int)blockDim.x>>5)) ? red[lane] : 0.f;
    #pragma unroll
    for (int o=16;o;o>>=1) v += __shfl_down_sync(0xffffffffu, v, o);
  }
  return v;
}
__device__ __forceinline__ unsigned short f2bf(float v){
  return __bfloat16_as_ushort(__float2bfloat16(v));
}

// ---------------- weight repack + accumulator reset -------------------------
__global__ void repack_k(const float* __restrict__ ew1, const float* __restrict__ ew2,
                         const float* __restrict__ dw1, const float* __restrict__ dw2,
                         const float* __restrict__ dw3, const float* __restrict__ w3,
                         const float* __restrict__ cb){
  int t = blockIdx.x*blockDim.x + threadIdx.x;
  int nt = gridDim.x*blockDim.x;
  if (blockIdx.x==0 && threadIdx.x<2) g_acc[threadIdx.x]=0.0;
  for (int i=t;i<512;i+=nt){
    int reg=i&1; int lane=(i>>1)&31; int ntv=(i>>6)&3; int kt=i>>8;
    int gg=lane>>2, tg=lane&3;
    int co = ntv*8+gg;
    int k0 = kt*16 + 2*tg + (reg?8:0);
    float w0=0.f, w1=0.f;
    if (k0<27){ int kh=k0/9, r=k0%9, kw=r/3, ci=r%3;
      w0 = ew1[((co*3+ci)*3+kh)*3+kw]; }
    if (k0+1<27){ int k1=k0+1; int kh=k1/9, r=k1%9, kw=r/3, ci=r%3;
      w1 = ew1[((co*3+ci)*3+kh)*3+kw]; }
    g_wfrag1[i] = (u32)f2bf(w0) | ((u32)f2bf(w1)<<16);
  }
  for (int i=t;i<18432;i+=nt){
    int reg=i&1; int lane=(i>>1)&31; int ntv=(i>>6)&7; int kt=(i>>9)&1; int tap=i>>10;
    int kh=tap/3, kw=tap%3;
    int gg=lane>>2, tg=lane&3;
    int co = ntv*8+gg;
    int ci0 = kt*16 + 2*tg + (reg?8:0);
    g_wfrag2[i] = (u32)f2bf(ew2[((co*32+ci0)*3+kh)*3+kw])
                | ((u32)f2bf(ew2[((co*32+ci0+1)*3+kh)*3+kw])<<16);
  }
  for (int i=t;i<4608;i+=nt){
    int reg=i&1; int lane=(i>>1)&31; int ntv=(i>>6)&7; int tap=i>>9;
    int kh=tap/3, kw=tap%3;
    int gg=lane>>2, tg=lane&3;
    int co = ntv*8+gg;
    int ci0 = 2*tg + (reg?8:0);
    g_wfragd1[i] = (u32)f2bf(dw1[((ci0*64+co)*3+kh)*3+kw])
                 | ((u32)f2bf(dw1[(((ci0+1)*64+co)*3+kh)*3+kw])<<16);
  }
  for (int i=t;i<9216;i+=nt){
    int tap = i>>10; int w_ = i & 1023;
    int reg = w_ & 1; int lane = (w_>>1)&31; int ntv = (w_>>6)&3; int kt = (w_>>8)&3;
    int kh = tap/3, kw = tap%3;
    int gg = lane>>2, tg = lane&3;
    int co = ntv*8+gg;
    int ci0 = kt*16 + 2*tg + (reg?8:0);
    g_wfrag[i] = (u32)f2bf(dw2[((ci0*32+co)*3+kh)*3+kw])
               | ((u32)f2bf(dw2[(((ci0+1)*32+co)*3+kh)*3+kw])<<16);
  }
  for (int i=t;i<1152;i+=nt){
    int reg=i&1; int lane=(i>>1)&31; int kt=(i>>6)&1; int tap=i>>7;
    int kh=tap/3, kw=tap%3;
    int gg=lane>>2, tg=lane&3;
    int co=gg;
    int ci0 = kt*16 + 2*tg + (reg?8:0);
    float w0=0.f, w1=0.f;
    if (co<3){
      w0 = dw3[((ci0*3+co)*3+(2-kh))*3+(2-kw)];
      w1 = dw3[(((ci0+1)*3+co)*3+(2-kh))*3+(2-kw)];
    }
    g_wfragd3[i] = (u32)f2bf(w0) | ((u32)f2bf(w1)<<16);
  }
  for (int i=t;i<512;i+=nt){
    int reg=i&1; int lane=(i>>1)&31; int ntv=(i>>6)&1; int kt=i>>7;
    int gg=lane>>2, tg=lane&3;
    int d = ntv*8+gg;
    int ci0 = kt*16 + 2*tg + (reg?8:0);
    g_wfragw3[i] = (u32)f2bf(w3[d*64+ci0]) | ((u32)f2bf(w3[d*64+ci0+1])<<16);
  }
  for (int i=t;i<4096;i+=nt){
    int reg=i&1; int lane=(i>>1)&31; int chunk=i>>6;
    int gg=lane>>2, tg=lane&3;
    int cw = chunk*8+gg;
    int d0 = 2*tg + (reg?8:0);
    g_wfragcb[i] = (u32)f2bf(cb[cw*16+d0]) | ((u32)f2bf(cb[cw*16+d0+1])<<16);
  }
  for (int k=t;k<512;k+=nt){
    float s=0.f;
    #pragma unroll
    for (int d=0;d<16;d++){ float e=cb[k*16+d]; s=fmaf(e,e,s); }
    g_nrm[k]=0.5f*s;
  }
}

// ---------------- enc1: 3->32 via mma; x staged in smem first ---------------
__global__ __launch_bounds__(128) void enc1_mma_k(const float* __restrict__ x,
                                                  const float* __restrict__ bias){
  constexpr int PXB = 80;
  __shared__ __align__(16) unsigned char As[64*PXB];
  __shared__ float xs[3][3][132];   // [ci][row r][col] window fp32
  __shared__ float bias_s[32];
  int tid = threadIdx.x, bx = blockIdx.x;
  int wchunk = bx & 1, ho = (bx>>1)&127, b = bx>>8;
  int wb0 = wchunk*64;
  if (tid<32) bias_s[tid]=bias[tid];
  const float* xb = x + (size_t)b*3*65536;
  // coalesced window stage (zero-fill OOB)
  for (int i=tid;i<3*3*132;i+=128){
    int ci=i/396, rem=i%396, r=rem/132, col=rem%132;
    int hi=2*ho-1+r, wi=2*wb0-1+col;
    float v = 0.f;
    if ((unsigned)hi<256u && (unsigned)wi<256u && col<130)
      v = xb[(size_t)ci*65536 + hi*256 + wi];
    xs[ci][r][col]=v;
  }
  __syncthreads();
  // build im2col A from smem
  for (int i=tid;i<2048;i+=128){
    int k=i>>6, px=i&63;
    unsigned short h=0;
    if (k<27){
      int kh=k/9, r=k%9, kw=r/3, ci=r%3;
      h = f2bf(xs[ci][kh][2*px+kw]);
    }
    *(unsigned short*)&As[px*PXB + k*2] = h;
  }
  __syncthreads();
  u32 aSm = smem_u32(As);
  int lane=tid&31, wid=tid>>5;
  int g=lane>>2, tig=lane&3;
  u32 laneRow=(u32)(lane&15), laneCol=(lane&16)?16u:0u;
  float c[4][4];
  #pragma unroll
  for (int ntv=0;ntv<4;ntv++){
    float bA=bias_s[ntv*8+2*tig], bB=bias_s[ntv*8+2*tig+1];
    c[ntv][0]=bA; c[ntv][1]=bB; c[ntv][2]=bA; c[ntv][3]=bB;
  }
  u32 abase = aSm + (u32)(wid*16+laneRow)*PXB + laneCol;
  #pragma unroll
  for (int kt=0;kt<2;kt++){
    u32 a0,a1,a2,a3;
    asm volatile("ldmatrix.sync.aligned.m8n8.x4.shared.b16 {%0,%1,%2,%3}, [%4];"
                 : "=r"(a0),"=r"(a1),"=r"(a2),"=r"(a3) : "r"(abase + kt*32));
    #pragma unroll
    for (int ntv=0;ntv<4;ntv++){
      uint2 bv = *(const uint2*)&g_wfrag1[(kt*4+ntv)*64 + lane*2];
      asm volatile("mma.sync.aligned.m16n8k16.row.col.f32.bf16.bf16.f32 "
                   "{%0,%1,%2,%3}, {%4,%5,%6,%7}, {%8,%9}, {%0,%1,%2,%3};"
                   : "+f"(c[ntv][0]),"+f"(c[ntv][1]),"+f"(c[ntv][2]),"+f"(c[ntv][3])
                   : "r"(a0),"r"(a1),"r"(a2),"r"(a3),"r"(bv.x),"r"(bv.y));
    }
  }
  int woA = wb0 + wid*16 + g, woB = woA + 8;
  unsigned short* rb = g_b1h + ((size_t)(b*128+ho))*128*32;
  unsigned short* pA = rb + (size_t)woA*32 + 2*tig;
  unsigned short* pB = rb + (size_t)woB*32 + 2*tig;
  #pragma unroll
  for (int ntv=0;ntv<4;ntv++){
    *(u32*)(pA + ntv*8) = bfpack(fmaxf(c[ntv][0],0.f), fmaxf(c[ntv][1],0.f));
    *(u32*)(pB + ntv*8) = bfpack(fmaxf(c[ntv][2],0.f), fmaxf(c[ntv][3],0.f));
  }
}

// ---------------- enc2: 32->64 k3 s2 p1 relu via mma bf16; bf16 out ---------
__global__ __launch_bounds__(128) void enc2_mma_k(const float* __restrict__ bias){
  constexpr int ROWB = 129*80;
  __shared__ __align__(16) unsigned char As[3*ROWB];
  __shared__ float bias_s[64];
  int tid = threadIdx.x, bx = blockIdx.x;
  int ho = bx & 63, b = bx >> 6;
  if (tid<64) bias_s[tid]=bias[tid];
  for (int i=tid;i<3*129*4;i+=128){
    int r=i/516, rem=i%516, px=rem>>2, ch=rem&3;
    int hi=2*ho-1+r, wi=px-1;
    uint4 v=make_uint4(0,0,0,0);
    if ((unsigned)hi<128u && (unsigned)wi<128u)
      v = *(const uint4*)&g_b1h[(((size_t)(b*128+hi))*128+wi)*32 + ch*8];
    *(uint4*)&As[r*ROWB + px*80 + ch*16] = v;
  }
  __syncthreads();
  u32 aSm = smem_u32(As);
  int lane = tid&31, wid = tid>>5;
  int g = lane>>2, tig = lane&3;
  float c[8][4];
  #pragma unroll
  for (int ntv=0;ntv<8;ntv++){
    float bA=bias_s[ntv*8+2*tig], bB=bias_s[ntv*8+2*tig+1];
    c[ntv][0]=bA; c[ntv][1]=bB; c[ntv][2]=bA; c[ntv][3]=bB;
  }
  u32 laneRow = (u32)(lane & 15);
  u32 laneCol = (lane & 16) ? 16u : 0u;
  #pragma unroll
  for (int kh=0;kh<3;kh++){
    #pragma unroll
    for (int kw=0;kw<3;kw++){
      int tap = kh*3+kw;
      #pragma unroll
      for (int kt=0;kt<2;kt++){
        u32 abase = aSm + kh*ROWB + (wid*32 + 2*laneRow + kw)*80 + kt*32 + laneCol;
        u32 a0,a1,a2,a3;
        asm volatile("ldmatrix.sync.aligned.m8n8.x4.shared.b16 {%0,%1,%2,%3}, [%4];"
                     : "=r"(a0),"=r"(a1),"=r"(a2),"=r"(a3) : "r"(abase));
        #pragma unroll
        for (int ntv=0;ntv<8;ntv++){
          uint2 bv = *(const uint2*)&g_wfrag2[tap*1024 + kt*512 + ntv*64 + lane*2];
          asm volatile("mma.sync.aligned.m16n8k16.row.col.f32.bf16.bf16.f32 "
                       "{%0,%1,%2,%3}, {%4,%5,%6,%7}, {%8,%9}, {%0,%1,%2,%3};"
                       : "+f"(c[ntv][0]),"+f"(c[ntv][1]),"+f"(c[ntv][2]),"+f"(c[ntv][3])
                       : "r"(a0),"r"(a1),"r"(a2),"r"(a3),"r"(bv.x),"r"(bv.y));
        }
      }
    }
  }
  int woA = wid*16+g, woB = woA+8;
  unsigned short* base = g_b2h + ((size_t)(b*64+ho))*64*64;
  unsigned short* pA = base + (size_t)woA*64 + 2*tig;
  unsigned short* pB = base + (size_t)woB*64 + 2*tig;
  #pragma unroll
  for (int ntv=0;ntv<8;ntv++){
    *(u32*)(pA + ntv*8) = bfpack(fmaxf(c[ntv][0],0.f), fmaxf(c[ntv][1],0.f));
    *(u32*)(pB + ntv*8) = bfpack(fmaxf(c[ntv][2],0.f), fmaxf(c[ntv][3],0.f));
  }
}

// ------------- VQ via mma: z-GEMM + scoring GEMM + quantize + loss ----------
__global__ __launch_bounds__(128) void vq_mma_k(const float* __restrict__ cb,
                                                const float* __restrict__ b3){
  __shared__ __align__(16) unsigned char As[64*144];
  __shared__ __align__(16) u32 CBf[4096];
  __shared__ __align__(8) float nrm_s[512];
  int tid = threadIdx.x;
  size_t base = (size_t)blockIdx.x*64;
  for (int i=tid;i<4096;i+=128) CBf[i]=g_wfragcb[i];
  for (int i=tid;i<512;i+=128) nrm_s[i]=g_nrm[i];
  for (int i=tid;i<512;i+=128){
    int px=i>>3, ch=i&7;
    uint4 v = *(const uint4*)&g_b2h[(base+px)*64 + ch*8];
    *(uint4*)&As[px*144 + ch*16] = v;
  }
  __syncthreads();
  u32 aSm=smem_u32(As), cbSm=smem_u32(CBf);
  int lane=tid&31, wid=tid>>5;
  int g=lane>>2, tig=lane&3;
  u32 laneRow=(u32)(lane&15), laneCol=(lane&16)?16u:0u;
  float zc[2][4];
  #pragma unroll
  for (int ntv=0;ntv<2;ntv++){
    float bA=b3[ntv*8+2*tig], bB=b3[ntv*8+2*tig+1];
    zc[ntv][0]=bA; zc[ntv][1]=bB; zc[ntv][2]=bA; zc[ntv][3]=bB;
  }
  u32 abase = aSm + (u32)(wid*16+laneRow)*144 + laneCol;
  #pragma unroll
  for (int kt=0;kt<4;kt++){
    u32 a0,a1,a2,a3;
    asm volatile("ldmatrix.sync.aligned.m8n8.x4.shared.b16 {%0,%1,%2,%3}, [%4];"
                 : "=r"(a0),"=r"(a1),"=r"(a2),"=r"(a3) : "r"(abase + kt*32));
    #pragma unroll
    for (int ntv=0;ntv<2;ntv++){
      uint2 bv = *(const uint2*)&g_wfragw3[(kt*2+ntv)*64 + lane*2];
      asm volatile("mma.sync.aligned.m16n8k16.row.col.f32.bf16.bf16.f32 "
                   "{%0,%1,%2,%3}, {%4,%5,%6,%7}, {%8,%9}, {%0,%1,%2,%3};"
                   : "+f"(zc[ntv][0]),"+f"(zc[ntv][1]),"+f"(zc[ntv][2]),"+f"(zc[ntv][3])
                   : "r"(a0),"r"(a1),"r"(a2),"r"(a3),"r"(bv.x),"r"(bv.y));
    }
  }
  u32 aZ0=bfpack(zc[0][0],zc[0][1]);
  u32 aZ1=bfpack(zc[0][2],zc[0][3]);
  u32 aZ2=bfpack(zc[1][0],zc[1][1]);
  u32 aZ3=bfpack(zc[1][2],zc[1][3]);
  float best0=-3.4e38f, best1=-3.4e38f; int bi0=0, bi1=0;
  for (int chunk=0;chunk<64;chunk++){
    float2 nk = *(const float2*)&nrm_s[chunk*8+2*tig];
    float s0=-nk.x, s1=-nk.y, s2=-nk.x, s3=-nk.y;
    u32 b0,b1;
    asm volatile("ld.shared.v2.u32 {%0,%1}, [%2];"
                 : "=r"(b0),"=r"(b1)
                 : "r"(cbSm + (chunk*64 + lane*2)*4));
    asm volatile("mma.sync.aligned.m16n8k16.row.col.f32.bf16.bf16.f32 "
                 "{%0,%1,%2,%3}, {%4,%5,%6,%7}, {%8,%9}, {%0,%1,%2,%3};"
                 : "+f"(s0),"+f"(s1),"+f"(s2),"+f"(s3)
                 : "r"(aZ0),"r"(aZ1),"r"(aZ2),"r"(aZ3),"r"(b0),"r"(b1));
    int i0 = chunk*8 + 2*tig;
    float cs; int ci;
    if (s1>s0){cs=s1;ci=i0+1;} else {cs=s0;ci=i0;}
    if (cs>best0){best0=cs;bi0=ci;}
    if (s3>s2){cs=s3;ci=i0+1;} else {cs=s2;ci=i0;}
    if (cs>best1){best1=cs;bi1=ci;}
  }
  #pragma unroll
  for (int off=1;off<4;off<<=1){
    float os=__shfl_xor_sync(0xffffffffu,best0,off);
    int   oi=__shfl_xor_sync(0xffffffffu,bi0,off);
    if (os>best0 || (os==best0 && oi<bi0)){best0=os;bi0=oi;}
    os=__shfl_xor_sync(0xffffffffu,best1,off);
    oi=__shfl_xor_sync(0xffffffffu,bi1,off);
    if (os>best1 || (os==best1 && oi<bi1)){best1=os;bi1=oi;}
  }
  size_t px0 = base + wid*16 + g, px1 = px0 + 8;
  float ls=0.f;
  {
    const float* e = cb + (size_t)bi0*16;
    *(u32*)&g_qh[px0*16 + tig*4]     = bfpack(e[tig*4],e[tig*4+1]);
    *(u32*)&g_qh[px0*16 + tig*4 + 2] = bfpack(e[tig*4+2],e[tig*4+3]);
    float d0=e[2*tig]-zc[0][0],   d1=e[2*tig+1]-zc[0][1];
    float d2=e[8+2*tig]-zc[1][0], d3=e[8+2*tig+1]-zc[1][1];
    ls = fmaf(d0,d0, fmaf(d1,d1, fmaf(d2,d2, fmaf(d3,d3, ls))));
  }
  {
    const float* e = cb + (size_t)bi1*16;
    *(u32*)&g_qh[px1*16 + tig*4]     = bfpack(e[tig*4],e[tig*4+1]);
    *(u32*)&g_qh[px1*16 + tig*4 + 2] = bfpack(e[tig*4+2],e[tig*4+3]);
    float d0=e[2*tig]-zc[0][2],   d1=e[2*tig+1]-zc[0][3];
    float d2=e[8+2*tig]-zc[1][2], d3=e[8+2*tig+1]-zc[1][3];
    ls = fmaf(d0,d0, fmaf(d1,d1, fmaf(d2,d2, fmaf(d3,d3, ls))));
  }
  float s = blockReduceSum(ls);
  if (tid==0) atomicAdd(&g_acc[0], (double)s);
}

// ------------- dec1: convT 16->64 via mma; 2 hb per block -------------------
__global__ __launch_bounds__(128) void dec1m_k(const float* __restrict__ bias){
  constexpr int ROWB = 65*48;
  __shared__ __align__(16) unsigned char As[3*ROWB];
  __shared__ float bias_s[64];
  int tid = threadIdx.x, bx = blockIdx.x;
  int hblk = bx & 31, b = bx >> 5;
  int hb0 = hblk*2;
  if (tid<64) bias_s[tid]=bias[tid];
  for (int i=tid;i<3*65*2;i+=128){
    int r=i/130, rem=i%130, px=rem>>1, hf=rem&1;
    int hi=hb0+r;
    uint4 v=make_uint4(0,0,0,0);
    if (hi<64 && px<64)
      v=*(const uint4*)&g_qh[(((size_t)(b*64+hi))*64+px)*16 + hf*8];
    *(uint4*)&As[r*ROWB+px*48+hf*16]=v;
  }
  __syncthreads();
  u32 aSm = smem_u32(As);
  int lane = tid&31, wid = tid>>5;
  int g = lane>>2, tig = lane&3;
  u32 laneRow = (u32)(lane & 15);
  u32 laneCol = (lane & 16) ? 16u : 0u;
  for (int hbo=0; hbo<2; hbo++){
    int hb = hb0 + hbo;
    for (int ph=0; ph<2; ph++){
      for (int pw=0; pw<2; pw++){
        float c[8][4];
        #pragma unroll
        for (int ntv=0;ntv<8;ntv++){
          float bA=bias_s[ntv*8+2*tig], bB=bias_s[ntv*8+2*tig+1];
          c[ntv][0]=bA; c[ntv][1]=bB; c[ntv][2]=bA; c[ntv][3]=bB;
        }
        int nkh = ph?2:1, nkw = pw?2:1;
        for (int a=0;a<nkh;a++){
          int kh = ph ? a*2 : 1;
          int rtap = (ph && a==0) ? 1 : 0;
          for (int cc=0;cc<nkw;cc++){
            int kw = pw ? cc*2 : 1;
            int shift = (pw && cc==0) ? 1 : 0;
            int tap = kh*3+kw;
            u32 abase = aSm + (hbo+rtap)*ROWB + (wid*16 + shift + laneRow)*48 + laneCol;
            u32 a0,a1,a2,a3;
            asm volatile("ldmatrix.sync.aligned.m8n8.x4.shared.b16 {%0,%1,%2,%3}, [%4];"
                         : "=r"(a0),"=r"(a1),"=r"(a2),"=r"(a3) : "r"(abase));
            #pragma unroll
            for (int ntv=0;ntv<8;ntv++){
              uint2 bv = *(const uint2*)&g_wfragd1[(tap*8+ntv)*64 + lane*2];
              asm volatile("mma.sync.aligned.m16n8k16.row.col.f32.bf16.bf16.f32 "
                           "{%0,%1,%2,%3}, {%4,%5,%6,%7}, {%8,%9}, {%0,%1,%2,%3};"
                           : "+f"(c[ntv][0]),"+f"(c[ntv][1]),"+f"(c[ntv][2]),"+f"(c[ntv][3])
                           : "r"(a0),"r"(a1),"r"(a2),"r"(a3),"r"(bv.x),"r"(bv.y));
            }
          }
        }
        int ho = 2*hb+ph;
        int wbA = wid*16+g, wbB = wbA+8;
        unsigned short* rb = g_d1h + ((size_t)(b*128+ho))*128*64;
        unsigned short* pA = rb + (size_t)(2*wbA+pw)*64 + 2*tig;
        unsigned short* pB = rb + (size_t)(2*wbB+pw)*64 + 2*tig;
        #pragma unroll
        for (int ntv=0;ntv<8;ntv++){
          *(u32*)(pA + ntv*8) = bfpack(fmaxf(c[ntv][0],0.f), fmaxf(c[ntv][1],0.f));
          *(u32*)(pB + ntv*8) = bfpack(fmaxf(c[ntv][2],0.f), fmaxf(c[ntv][3],0.f));
        }
      }
    }
  }
}

// ------------- dec2: convT 64->32 via mma; 2 hb per block -------------------
__global__ __launch_bounds__(128) void dec2m_k(const float* __restrict__ bias){
  constexpr int ROWB = 65*144;
  __shared__ __align__(16) unsigned char As[3*ROWB];
  __shared__ float bias_s[32];
  int tid = threadIdx.x, bx = blockIdx.x;
  int wchunk = bx & 1, hblk = (bx>>1)&63, b = bx>>7;
  int wb0 = wchunk*64;
  int hb0 = hblk*2;
  if (tid<32) bias_s[tid]=bias[tid];
  for (int i=tid;i<3*65*8;i+=128){
    int r = i/520, rem = i%520, px = rem>>3, ch = rem&7;
    int hi = hb0 + r;
    int wi = wb0 + px;
    uint4 v = make_uint4(0,0,0,0);
    if (hi<128 && wi<128)
      v = *(const uint4*)&g_d1h[(((size_t)(b*128+hi))*128+wi)*64 + ch*8];
    *(uint4*)&As[r*ROWB + px*144 + ch*16] = v;
  }
  __syncthreads();
  u32 aSm = smem_u32(As);
  int lane = tid & 31, wid = tid>>5;
  int g = lane>>2, tig = lane&3;
  u32 laneRow = (u32)(lane & 15);
  u32 laneCol = (lane & 16) ? 16u : 0u;
  for (int hbo=0; hbo<2; hbo++){
    int hb = hb0 + hbo;
    for (int ph=0; ph<2; ph++){
      for (int pw=0; pw<2; pw++){
        float c[4][4];
        #pragma unroll
        for (int ntv=0;ntv<4;ntv++){
          float bA = bias_s[ntv*8+2*tig], bB = bias_s[ntv*8+2*tig+1];
          c[ntv][0]=bA; c[ntv][1]=bB; c[ntv][2]=bA; c[ntv][3]=bB;
        }
        int nkh = ph?2:1, nkw = pw?2:1;
        for (int a=0;a<nkh;a++){
          int kh = ph ? a*2 : 1;
          int rtap = (ph && a==0) ? 1 : 0;
          for (int cc=0;cc<nkw;cc++){
            int kw = pw ? cc*2 : 1;
            int shift = (pw && cc==0) ? 1 : 0;
            int tap = kh*3+kw;
            u32 abase = aSm + (hbo+rtap)*ROWB + (wid*16 + shift + laneRow)*144 + laneCol;
            #pragma unroll
            for (int kt=0;kt<4;kt++){
              u32 a0,a1,a2,a3;
              asm volatile("ldmatrix.sync.aligned.m8n8.x4.shared.b16 {%0,%1,%2,%3}, [%4];"
                           : "=r"(a0),"=r"(a1),"=r"(a2),"=r"(a3)
                           : "r"(abase + kt*32));
              #pragma unroll
              for (int ntv=0;ntv<4;ntv++){
                uint2 bv = *(const uint2*)&g_wfrag[((tap*4+kt)*4+ntv)*64 + lane*2];
                asm volatile("mma.sync.aligned.m16n8k16.row.col.f32.bf16.bf16.f32 "
                             "{%0,%1,%2,%3}, {%4,%5,%6,%7}, {%8,%9}, {%0,%1,%2,%3};"
                             : "+f"(c[ntv][0]),"+f"(c[ntv][1]),"+f"(c[ntv][2]),"+f"(c[ntv][3])
                             : "r"(a0),"r"(a1),"r"(a2),"r"(a3),"r"(bv.x),"r"(bv.y));
              }
            }
          }
        }
        int ho = 2*hb+ph;
        int wbA = wb0 + wid*16 + g, wbB = wbA + 8;
        unsigned short* rowBase = g_d2h + ((size_t)(b*256+ho))*256*32;
        unsigned short* pA = rowBase + (size_t)(2*wbA+pw)*32 + 2*tig;
        unsigned short* pB = rowBase + (size_t)(2*wbB+pw)*32 + 2*tig;
        #pragma unroll
        for (int ntv=0;ntv<4;ntv++){
          *(u32*)(pA + ntv*8) = bfpack(fmaxf(c[ntv][0],0.f), fmaxf(c[ntv][1],0.f));
          *(u32*)(pB + ntv*8) = bfpack(fmaxf(c[ntv][2],0.f), fmaxf(c[ntv][3],0.f));
        }
      }
    }
  }
}

// ------------- dec3: conv 32->3 via mma, 4 output rows/block + fused MSE ----
__global__ __launch_bounds__(128) void dec3_mma_k(const float* __restrict__ x,
                                                  const float* __restrict__ bias){
  constexpr int PXB = 80;
  __shared__ __align__(16) unsigned char As[6*66*PXB];   // 6 rows x 66 px
  __shared__ float bias_s[3];
  int tid = threadIdx.x, bx = blockIdx.x;
  int wchunk = bx & 3, hrow = (bx>>2)&63, b = bx>>8;
  int wb0 = wchunk*64;
  int ho0 = hrow*4;
  if (tid<3) bias_s[tid]=bias[tid];
  for (int i=tid;i<6*66*4;i+=128){
    int r=i/264, rem=i%264, px=rem>>2, q=rem&3;
    int hi=ho0-1+r, wi=wb0-1+px;
    uint4 v=make_uint4(0,0,0,0);
    if ((unsigned)hi<256u && (unsigned)wi<256u)
      v=*(const uint4*)&g_d2h[(((size_t)(b*256+hi))*256+wi)*32 + q*8];
    *(uint4*)&As[(r*66+px)*PXB + q*16]=v;
  }
  __syncthreads();
  u32 aSm=smem_u32(As);
  int lane=tid&31, wid=tid>>5;
  int g=lane>>2, tig=lane&3;
  u32 laneRow=(u32)(lane&15);
  u32 laneCol=(lane&16)?16u:0u;
  int co0 = 2*tig, co1 = co0+1;
  float ls = 0.f;
  for (int r=0;r<4;r++){
    float c[4]={0.f,0.f,0.f,0.f};
    #pragma unroll
    for (int kh=0;kh<3;kh++){
      #pragma unroll
      for (int kw=0;kw<3;kw++){
        int tap=kh*3+kw;
        u32 abase = aSm + (u32)((r+kh)*66 + wid*16 + kw + laneRow)*PXB + laneCol;
        #pragma unroll
        for (int kt=0;kt<2;kt++){
          u32 a0,a1,a2,a3;
          asm volatile("ldmatrix.sync.aligned.m8n8.x4.shared.b16 {%0,%1,%2,%3}, [%4];"
                       : "=r"(a0),"=r"(a1),"=r"(a2),"=r"(a3) : "r"(abase + kt*32));
          uint2 bv = *(const uint2*)&g_wfragd3[(tap*2+kt)*64 + lane*2];
          asm volatile("mma.sync.aligned.m16n8k16.row.col.f32.bf16.bf16.f32 "
                       "{%0,%1,%2,%3}, {%4,%5,%6,%7}, {%8,%9}, {%0,%1,%2,%3};"
                       : "+f"(c[0]),"+f"(c[1]),"+f"(c[2]),"+f"(c[3])
                       : "r"(a0),"r"(a1),"r"(a2),"r"(a3),"r"(bv.x),"r"(bv.y));
        }
      }
    }
    int ho = ho0 + r;
    int pxA = wb0 + wid*16 + g, pxB = pxA + 8;
    const float* xb = x + (size_t)b*3*65536 + ho*256;
    if (co0 < 3){
      float d0 = c[0] + bias_s[co0] - xb[(size_t)co0*65536 + pxA];
      float d1 = c[2] + bias_s[co0] - xb[(size_t)co0*65536 + pxB];
      ls = fmaf(d0,d0, fmaf(d1,d1, ls));
    }
    if (co1 < 3){
      float d0 = c[1] + bias_s[co1] - xb[(size_t)co1*65536 + pxA];
      float d1 = c[3] + bias_s[co1] - xb[(size_t)co1*65536 + pxB];
      ls = fmaf(d0,d0, fmaf(d1,d1, ls));
    }
  }
  float s = blockReduceSum(ls);
  if (tid==0) atomicAdd(&g_acc[1], (double)s);
}

// ------------- finalize -----------------------------------------------------
__global__ void final_k(float* __restrict__ out){
  double vq  = g_acc[0];
  double rec = g_acc[1];
  float e_q  = (float)(1.25 * vq / 4194304.0);
  float mse  = (float)(rec / 12582912.0);
  out[0] = e_q;
  out[1] = mse;
  out[2] = mse;
}

// ---------------- launch ----------------------------------------------------
extern "C" void kernel_launch(void* const* d_in, const int* in_sizes, int n_in,
                              void* d_out, int out_size){
  const float* x   = (const float*)d_in[0];
  const float* ew1 = (const float*)d_in[1];
  const float* eb1 = (const float*)d_in[2];
  const float* ew2 = (const float*)d_in[3];
  const float* eb2 = (const float*)d_in[4];
  const float* ew3 = (const float*)d_in[5];
  const float* eb3 = (const float*)d_in[6];
  const float* cb  = (const float*)d_in[7];
  const float* dw1 = (const float*)d_in[8];
  const float* db1 = (const float*)d_in[9];
  const float* dw2 = (const float*)d_in[10];
  const float* db2 = (const float*)d_in[11];
  const float* dw3 = (const float*)d_in[12];
  const float* db3 = (const float*)d_in[13];
  float* out = (float*)d_out;

  repack_k<<<64,256>>>(ew1, ew2, dw1, dw2, dw3, ew3, cb);
  enc1_mma_k<<<16384,128>>>(x, eb1);
  enc2_mma_k<<<4096,128>>>(eb2);
  vq_mma_k<<<4096,128>>>(cb, eb3);
  dec1m_k<<<2048,128>>>(db1);
  dec2m_k<<<8192,128>>>(db2);
  dec3_mma_k<<<16384,128>>>(x, db3);
  final_k<<<1,1>>>(out);
}

// round 15
// speedup vs baseline: 1.0607x; 1.0607x over previous
#include <cuda_runtime.h>
#include <cuda_bf16.h>
#include <cstdint>

typedef unsigned long long u64;
typedef unsigned int u32;

// ---------------- scratch (device globals; no allocations allowed) ----------
__device__ unsigned short g_b1h[(size_t)64*128*128*32];  // enc1 out NHWC bf16
__device__ unsigned short g_b2h[(size_t)64*64*64*64];    // enc2 out NHWC bf16
__device__ unsigned short g_qh[(size_t)64*64*64*16];     // quantized NHWC bf16
__device__ unsigned short g_d1h[(size_t)64*128*128*64];  // dec1 out NHWC bf16
__device__ unsigned short g_d2h[(size_t)64*256*256*32];  // dec2 out NHWC bf16

__device__ u32   g_wfrag1[512];     // enc1 w  B-frags
__device__ u32   g_wfrag2[18432];   // enc2 w  B-frags
__device__ u32   g_wfragd1[4608];   // dec1 w  B-frags
__device__ u32   g_wfrag[9216];     // dec2 w  B-frags
__device__ u32   g_wfragd3[1152];   // dec3 w  B-frags (flip baked)
__device__ u32   g_wfragw3[512];    // enc3(1x1) w B-frags
__device__ u32   g_wfragcb[4096];   // codebook B-frags
__device__ float g_nrm[512];        // 0.5*||e_k||^2 (fp32)
__device__ double g_acc[2];         // [0]=vq sq-sum, [1]=recon sq-sum

// ---------------- helpers ----------------------------------------------------
__device__ __forceinline__ u32 bfpack(float lo, float hi){
  u32 r; asm("cvt.rn.bf16x2.f32 %0, %1, %2;" : "=r"(r) : "f"(hi), "f"(lo));
  return r;
}
__device__ __forceinline__ u32 smem_u32(const void* p){
  u32 a; asm("{ .reg .u64 t; cvta.to.shared.u64 t, %1; cvt.u32.u64 %0, t; }"
             : "=r"(a) : "l"(p));
  return a;
}
__device__ __forceinline__ float blockReduceSum(float v){
  __shared__ float red[32];
  #pragma unroll
  for (int o=16;o;o>>=1) v += __shfl_down_sync(0xffffffffu, v, o);
  int lane = threadIdx.x & 31, w = threadIdx.x >> 5;
  if (lane==0) red[w]=v;
  __syncthreads();
  if (w==0){
    v = (lane < ((int)blockDim.x>>5)) ? red[lane] : 0.f;
    #pragma unroll
    for (int o=16;o;o>>=1) v += __shfl_down_sync(0xffffffffu, v, o);
  }
  return v;
}
__device__ __forceinline__ unsigned short f2bf(float v){
  return __bfloat16_as_ushort(__float2bfloat16(v));
}

// ---------------- weight repack + accumulator reset -------------------------
__global__ void repack_k(const float* __restrict__ ew1, const float* __restrict__ ew2,
                         const float* __restrict__ dw1, const float* __restrict__ dw2,
                         const float* __restrict__ dw3, const float* __restrict__ w3,
                         const float* __restrict__ cb){
  int t = blockIdx.x*blockDim.x + threadIdx.x;
  int nt = gridDim.x*blockDim.x;
  if (blockIdx.x==0 && threadIdx.x<2) g_acc[threadIdx.x]=0.0;
  for (int i=t;i<512;i+=nt){
    int reg=i&1; int lane=(i>>1)&31; int ntv=(i>>6)&3; int kt=i>>8;
    int gg=lane>>2, tg=lane&3;
    int co = ntv*8+gg;
    int k0 = kt*16 + 2*tg + (reg?8:0);
    float w0=0.f, w1=0.f;
    if (k0<27){ int kh=k0/9, r=k0%9, kw=r/3, ci=r%3;
      w0 = ew1[((co*3+ci)*3+kh)*3+kw]; }
    if (k0+1<27){ int k1=k0+1; int kh=k1/9, r=k1%9, kw=r/3, ci=r%3;
      w1 = ew1[((co*3+ci)*3+kh)*3+kw]; }
    g_wfrag1[i] = (u32)f2bf(w0) | ((u32)f2bf(w1)<<16);
  }
  for (int i=t;i<18432;i+=nt){
    int reg=i&1; int lane=(i>>1)&31; int ntv=(i>>6)&7; int kt=(i>>9)&1; int tap=i>>10;
    int kh=tap/3, kw=tap%3;
    int gg=lane>>2, tg=lane&3;
    int co = ntv*8+gg;
    int ci0 = kt*16 + 2*tg + (reg?8:0);
    g_wfrag2[i] = (u32)f2bf(ew2[((co*32+ci0)*3+kh)*3+kw])
                | ((u32)f2bf(ew2[((co*32+ci0+1)*3+kh)*3+kw])<<16);
  }
  for (int i=t;i<4608;i+=nt){
    int reg=i&1; int lane=(i>>1)&31; int ntv=(i>>6)&7; int tap=i>>9;
    int kh=tap/3, kw=tap%3;
    int gg=lane>>2, tg=lane&3;
    int co = ntv*8+gg;
    int ci0 = 2*tg + (reg?8:0);
    g_wfragd1[i] = (u32)f2bf(dw1[((ci0*64+co)*3+kh)*3+kw])
                 | ((u32)f2bf(dw1[(((ci0+1)*64+co)*3+kh)*3+kw])<<16);
  }
  for (int i=t;i<9216;i+=nt){
    int tap = i>>10; int w_ = i & 1023;
    int reg = w_ & 1; int lane = (w_>>1)&31; int ntv = (w_>>6)&3; int kt = (w_>>8)&3;
    int kh = tap/3, kw = tap%3;
    int gg = lane>>2, tg = lane&3;
    int co = ntv*8+gg;
    int ci0 = kt*16 + 2*tg + (reg?8:0);
    g_wfrag[i] = (u32)f2bf(dw2[((ci0*32+co)*3+kh)*3+kw])
               | ((u32)f2bf(dw2[(((ci0+1)*32+co)*3+kh)*3+kw])<<16);
  }
  for (int i=t;i<1152;i+=nt){
    int reg=i&1; int lane=(i>>1)&31; int kt=(i>>6)&1; int tap=i>>7;
    int kh=tap/3, kw=tap%3;
    int gg=lane>>2, tg=lane&3;
    int co=gg;
    int ci0 = kt*16 + 2*tg + (reg?8:0);
    float w0=0.f, w1=0.f;
    if (co<3){
      w0 = dw3[((ci0*3+co)*3+(2-kh))*3+(2-kw)];
      w1 = dw3[(((ci0+1)*3+co)*3+(2-kh))*3+(2-kw)];
    }
    g_wfragd3[i] = (u32)f2bf(w0) | ((u32)f2bf(w1)<<16);
  }
  for (int i=t;i<512;i+=nt){
    int reg=i&1; int lane=(i>>1)&31; int ntv=(i>>6)&1; int kt=i>>7;
    int gg=lane>>2, tg=lane&3;
    int d = ntv*8+gg;
    int ci0 = kt*16 + 2*tg + (reg?8:0);
    g_wfragw3[i] = (u32)f2bf(w3[d*64+ci0]) | ((u32)f2bf(w3[d*64+ci0+1])<<16);
  }
  for (int i=t;i<4096;i+=nt){
    int reg=i&1; int lane=(i>>1)&31; int chunk=i>>6;
    int gg=lane>>2, tg=lane&3;
    int cw = chunk*8+gg;
    int d0 = 2*tg + (reg?8:0);
    g_wfragcb[i] = (u32)f2bf(cb[cw*16+d0]) | ((u32)f2bf(cb[cw*16+d0+1])<<16);
  }
  for (int k=t;k<512;k+=nt){
    float s=0.f;
    #pragma unroll
    for (int d=0;d<16;d++){ float e=cb[k*16+d]; s=fmaf(e,e,s); }
    g_nrm[k]=0.5f*s;
  }
}

// ---------------- enc1: 3->32 via mma; im2col with smem offset table --------
__global__ __launch_bounds__(128) void enc1_mma_k(const float* __restrict__ x,
                                                  const float* __restrict__ bias){
  constexpr int PXB = 80;
  __shared__ __align__(16) unsigned char As[64*PXB];
  __shared__ float bias_s[32];
  __shared__ int offs[27], khs[27], kws[27];
  int tid = threadIdx.x, bx = blockIdx.x;
  int wchunk = bx & 1, ho = (bx>>1)&127, b = bx>>8;
  int wb0 = wchunk*64;
  if (tid<32) bias_s[tid]=bias[tid];
  if (tid<27){
    int kh=tid/9, r=tid%9, kw=r/3, ci=r%3;
    offs[tid] = ci*65536 + kh*256 + kw;
    khs[tid] = kh; kws[tid] = kw;
  }
  __syncthreads();
  const float* xb = x + (size_t)b*3*65536;
  int hbase = 2*ho-1, wbase = 2*wb0-1;
  int C = hbase*256 + wbase;
  for (int i=tid;i<2048;i+=128){
    int k=i>>6, px=i&63;
    unsigned short h=0;
    if (k<27){
      int hi = hbase + khs[k], wi = wbase + 2*px + kws[k];
      if ((unsigned)hi<256u && (unsigned)wi<256u)
        h = f2bf(xb[offs[k] + C + 2*px]);
    }
    *(unsigned short*)&As[px*PXB + k*2] = h;
  }
  __syncthreads();
  u32 aSm = smem_u32(As);
  int lane=tid&31, wid=tid>>5;
  int g=lane>>2, tig=lane&3;
  u32 laneRow=(u32)(lane&15), laneCol=(lane&16)?16u:0u;
  float c[4][4];
  #pragma unroll
  for (int ntv=0;ntv<4;ntv++){
    float bA=bias_s[ntv*8+2*tig], bB=bias_s[ntv*8+2*tig+1];
    c[ntv][0]=bA; c[ntv][1]=bB; c[ntv][2]=bA; c[ntv][3]=bB;
  }
  u32 abase = aSm + (u32)(wid*16+laneRow)*PXB + laneCol;
  #pragma unroll
  for (int kt=0;kt<2;kt++){
    u32 a0,a1,a2,a3;
    asm volatile("ldmatrix.sync.aligned.m8n8.x4.shared.b16 {%0,%1,%2,%3}, [%4];"
                 : "=r"(a0),"=r"(a1),"=r"(a2),"=r"(a3) : "r"(abase + kt*32));
    #pragma unroll
    for (int ntv=0;ntv<4;ntv++){
      uint2 bv = *(const uint2*)&g_wfrag1[(kt*4+ntv)*64 + lane*2];
      asm volatile("mma.sync.aligned.m16n8k16.row.col.f32.bf16.bf16.f32 "
                   "{%0,%1,%2,%3}, {%4,%5,%6,%7}, {%8,%9}, {%0,%1,%2,%3};"
                   : "+f"(c[ntv][0]),"+f"(c[ntv][1]),"+f"(c[ntv][2]),"+f"(c[ntv][3])
                   : "r"(a0),"r"(a1),"r"(a2),"r"(a3),"r"(bv.x),"r"(bv.y));
    }
  }
  int woA = wb0 + wid*16 + g, woB = woA + 8;
  unsigned short* rb = g_b1h + ((size_t)(b*128+ho))*128*32;
  unsigned short* pA = rb + (size_t)woA*32 + 2*tig;
  unsigned short* pB = rb + (size_t)woB*32 + 2*tig;
  #pragma unroll
  for (int ntv=0;ntv<4;ntv++){
    *(u32*)(pA + ntv*8) = bfpack(fmaxf(c[ntv][0],0.f), fmaxf(c[ntv][1],0.f));
    *(u32*)(pB + ntv*8) = bfpack(fmaxf(c[ntv][2],0.f), fmaxf(c[ntv][3],0.f));
  }
}

// ---------------- enc2: 32->64 k3 s2 p1 relu via mma bf16; bf16 out ---------
__global__ __launch_bounds__(128) void enc2_mma_k(const float* __restrict__ bias){
  constexpr int ROWB = 129*80;
  __shared__ __align__(16) unsigned char As[3*ROWB];
  __shared__ float bias_s[64];
  int tid = threadIdx.x, bx = blockIdx.x;
  int ho = bx & 63, b = bx >> 6;
  if (tid<64) bias_s[tid]=bias[tid];
  for (int i=tid;i<3*129*4;i+=128){
    int r=i/516, rem=i%516, px=rem>>2, ch=rem&3;
    int hi=2*ho-1+r, wi=px-1;
    uint4 v=make_uint4(0,0,0,0);
    if ((unsigned)hi<128u && (unsigned)wi<128u)
      v = *(const uint4*)&g_b1h[(((size_t)(b*128+hi))*128+wi)*32 + ch*8];
    *(uint4*)&As[r*ROWB + px*80 + ch*16] = v;
  }
  __syncthreads();
  u32 aSm = smem_u32(As);
  int lane = tid&31, wid = tid>>5;
  int g = lane>>2, tig = lane&3;
  float c[8][4];
  #pragma unroll
  for (int ntv=0;ntv<8;ntv++){
    float bA=bias_s[ntv*8+2*tig], bB=bias_s[ntv*8+2*tig+1];
    c[ntv][0]=bA; c[ntv][1]=bB; c[ntv][2]=bA; c[ntv][3]=bB;
  }
  u32 laneRow = (u32)(lane & 15);
  u32 laneCol = (lane & 16) ? 16u : 0u;
  #pragma unroll
  for (int kh=0;kh<3;kh++){
    #pragma unroll
    for (int kw=0;kw<3;kw++){
      int tap = kh*3+kw;
      #pragma unroll
      for (int kt=0;kt<2;kt++){
        u32 abase = aSm + kh*ROWB + (wid*32 + 2*laneRow + kw)*80 + kt*32 + laneCol;
        u32 a0,a1,a2,a3;
        asm volatile("ldmatrix.sync.aligned.m8n8.x4.shared.b16 {%0,%1,%2,%3}, [%4];"
                     : "=r"(a0),"=r"(a1),"=r"(a2),"=r"(a3) : "r"(abase));
        #pragma unroll
        for (int ntv=0;ntv<8;ntv++){
          uint2 bv = *(const uint2*)&g_wfrag2[tap*1024 + kt*512 + ntv*64 + lane*2];
          asm volatile("mma.sync.aligned.m16n8k16.row.col.f32.bf16.bf16.f32 "
                       "{%0,%1,%2,%3}, {%4,%5,%6,%7}, {%8,%9}, {%0,%1,%2,%3};"
                       : "+f"(c[ntv][0]),"+f"(c[ntv][1]),"+f"(c[ntv][2]),"+f"(c[ntv][3])
                       : "r"(a0),"r"(a1),"r"(a2),"r"(a3),"r"(bv.x),"r"(bv.y));
        }
      }
    }
  }
  int woA = wid*16+g, woB = woA+8;
  unsigned short* base = g_b2h + ((size_t)(b*64+ho))*64*64;
  unsigned short* pA = base + (size_t)woA*64 + 2*tig;
  unsigned short* pB = base + (size_t)woB*64 + 2*tig;
  #pragma unroll
  for (int ntv=0;ntv<8;ntv++){
    *(u32*)(pA + ntv*8) = bfpack(fmaxf(c[ntv][0],0.f), fmaxf(c[ntv][1],0.f));
    *(u32*)(pB + ntv*8) = bfpack(fmaxf(c[ntv][2],0.f), fmaxf(c[ntv][3],0.f));
  }
}

// ------------- VQ via mma: z-GEMM + scoring GEMM + quantize + loss ----------
__global__ __launch_bounds__(128) void vq_mma_k(const float* __restrict__ cb,
                                                const float* __restrict__ b3){
  __shared__ __align__(16) unsigned char As[64*144];
  __shared__ __align__(16) u32 CBf[4096];
  __shared__ __align__(8) float nrm_s[512];
  int tid = threadIdx.x;
  size_t base = (size_t)blockIdx.x*64;
  for (int i=tid;i<4096;i+=128) CBf[i]=g_wfragcb[i];
  for (int i=tid;i<512;i+=128) nrm_s[i]=g_nrm[i];
  for (int i=tid;i<512;i+=128){
    int px=i>>3, ch=i&7;
    uint4 v = *(const uint4*)&g_b2h[(base+px)*64 + ch*8];
    *(uint4*)&As[px*144 + ch*16] = v;
  }
  __syncthreads();
  u32 aSm=smem_u32(As), cbSm=smem_u32(CBf);
  int lane=tid&31, wid=tid>>5;
  int g=lane>>2, tig=lane&3;
  u32 laneRow=(u32)(lane&15), laneCol=(lane&16)?16u:0u;
  float zc[2][4];
  #pragma unroll
  for (int ntv=0;ntv<2;ntv++){
    float bA=b3[ntv*8+2*tig], bB=b3[ntv*8+2*tig+1];
    zc[ntv][0]=bA; zc[ntv][1]=bB; zc[ntv][2]=bA; zc[ntv][3]=bB;
  }
  u32 abase = aSm + (u32)(wid*16+laneRow)*144 + laneCol;
  #pragma unroll
  for (int kt=0;kt<4;kt++){
    u32 a0,a1,a2,a3;
    asm volatile("ldmatrix.sync.aligned.m8n8.x4.shared.b16 {%0,%1,%2,%3}, [%4];"
                 : "=r"(a0),"=r"(a1),"=r"(a2),"=r"(a3) : "r"(abase + kt*32));
    #pragma unroll
    for (int ntv=0;ntv<2;ntv++){
      uint2 bv = *(const uint2*)&g_wfragw3[(kt*2+ntv)*64 + lane*2];
      asm volatile("mma.sync.aligned.m16n8k16.row.col.f32.bf16.bf16.f32 "
                   "{%0,%1,%2,%3}, {%4,%5,%6,%7}, {%8,%9}, {%0,%1,%2,%3};"
                   : "+f"(zc[ntv][0]),"+f"(zc[ntv][1]),"+f"(zc[ntv][2]),"+f"(zc[ntv][3])
                   : "r"(a0),"r"(a1),"r"(a2),"r"(a3),"r"(bv.x),"r"(bv.y));
    }
  }
  u32 aZ0=bfpack(zc[0][0],zc[0][1]);
  u32 aZ1=bfpack(zc[0][2],zc[0][3]);
  u32 aZ2=bfpack(zc[1][0],zc[1][1]);
  u32 aZ3=bfpack(zc[1][2],zc[1][3]);
  float best0=-3.4e38f, best1=-3.4e38f; int bi0=0, bi1=0;
  for (int chunk=0;chunk<64;chunk++){
    float2 nk = *(const float2*)&nrm_s[chunk*8+2*tig];
    float s0=-nk.x, s1=-nk.y, s2=-nk.x, s3=-nk.y;
    u32 b0,b1;
    asm volatile("ld.shared.v2.u32 {%0,%1}, [%2];"
                 : "=r"(b0),"=r"(b1)
                 : "r"(cbSm + (chunk*64 + lane*2)*4));
    asm volatile("mma.sync.aligned.m16n8k16.row.col.f32.bf16.bf16.f32 "
                 "{%0,%1,%2,%3}, {%4,%5,%6,%7}, {%8,%9}, {%0,%1,%2,%3};"
                 : "+f"(s0),"+f"(s1),"+f"(s2),"+f"(s3)
                 : "r"(aZ0),"r"(aZ1),"r"(aZ2),"r"(aZ3),"r"(b0),"r"(b1));
    int i0 = chunk*8 + 2*tig;
    float cs; int ci;
    if (s1>s0){cs=s1;ci=i0+1;} else {cs=s0;ci=i0;}
    if (cs>best0){best0=cs;bi0=ci;}
    if (s3>s2){cs=s3;ci=i0+1;} else {cs=s2;ci=i0;}
    if (cs>best1){best1=cs;bi1=ci;}
  }
  #pragma unroll
  for (int off=1;off<4;off<<=1){
    float os=__shfl_xor_sync(0xffffffffu,best0,off);
    int   oi=__shfl_xor_sync(0xffffffffu,bi0,off);
    if (os>best0 || (os==best0 && oi<bi0)){best0=os;bi0=oi;}
    os=__shfl_xor_sync(0xffffffffu,best1,off);
    oi=__shfl_xor_sync(0xffffffffu,bi1,off);
    if (os>best1 || (os==best1 && oi<bi1)){best1=os;bi1=oi;}
  }
  size_t px0 = base + wid*16 + g, px1 = px0 + 8;
  float ls=0.f;
  {
    const float* e = cb + (size_t)bi0*16;
    *(u32*)&g_qh[px0*16 + tig*4]     = bfpack(e[tig*4],e[tig*4+1]);
    *(u32*)&g_qh[px0*16 + tig*4 + 2] = bfpack(e[tig*4+2],e[tig*4+3]);
    float d0=e[2*tig]-zc[0][0],   d1=e[2*tig+1]-zc[0][1];
    float d2=e[8+2*tig]-zc[1][0], d3=e[8+2*tig+1]-zc[1][1];
    ls = fmaf(d0,d0, fmaf(d1,d1, fmaf(d2,d2, fmaf(d3,d3, ls))));
  }
  {
    const float* e = cb + (size_t)bi1*16;
    *(u32*)&g_qh[px1*16 + tig*4]     = bfpack(e[tig*4],e[tig*4+1]);
    *(u32*)&g_qh[px1*16 + tig*4 + 2] = bfpack(e[tig*4+2],e[tig*4+3]);
    float d0=e[2*tig]-zc[0][2],   d1=e[2*tig+1]-zc[0][3];
    float d2=e[8+2*tig]-zc[1][2], d3=e[8+2*tig+1]-zc[1][3];
    ls = fmaf(d0,d0, fmaf(d1,d1, fmaf(d2,d2, fmaf(d3,d3, ls))));
  }
  float s = blockReduceSum(ls);
  if (tid==0) atomicAdd(&g_acc[0], (double)s);
}

// ------------- dec1: convT 16->64 via mma, 4 parities merged, B from global -
__global__ __launch_bounds__(128) void dec1m_k(const float* __restrict__ bias){
  constexpr int ROWB = 65*48;
  __shared__ __align__(16) unsigned char As[2*ROWB];
  __shared__ float bias_s[64];
  int tid = threadIdx.x, bx = blockIdx.x;
  int hb = bx & 63, b = bx >> 6;
  if (tid<64) bias_s[tid]=bias[tid];
  for (int i=tid;i<2*65*2;i+=128){
    int r=i/130, rem=i%130, px=rem>>1, hf=rem&1;
    int hi=hb+r;
    uint4 v=make_uint4(0,0,0,0);
    if (hi<64 && px<64)
      v=*(const uint4*)&g_qh[(((size_t)(b*64+hi))*64+px)*16 + hf*8];
    *(uint4*)&As[r*ROWB+px*48+hf*16]=v;
  }
  __syncthreads();
  u32 aSm = smem_u32(As);
  int lane = tid&31, wid = tid>>5;
  int g = lane>>2, tig = lane&3;
  u32 laneRow = (u32)(lane & 15);
  u32 laneCol = (lane & 16) ? 16u : 0u;
  for (int ph=0; ph<2; ph++){
    for (int pw=0; pw<2; pw++){
      float c[8][4];
      #pragma unroll
      for (int ntv=0;ntv<8;ntv++){
        float bA=bias_s[ntv*8+2*tig], bB=bias_s[ntv*8+2*tig+1];
        c[ntv][0]=bA; c[ntv][1]=bB; c[ntv][2]=bA; c[ntv][3]=bB;
      }
      int nkh = ph?2:1, nkw = pw?2:1;
      for (int a=0;a<nkh;a++){
        int kh = ph ? a*2 : 1;
        int rtap = (ph && a==0) ? 1 : 0;
        for (int cc=0;cc<nkw;cc++){
          int kw = pw ? cc*2 : 1;
          int shift = (pw && cc==0) ? 1 : 0;
          int tap = kh*3+kw;
          u32 abase = aSm + rtap*ROWB + (wid*16 + shift + laneRow)*48 + laneCol;
          u32 a0,a1,a2,a3;
          asm volatile("ldmatrix.sync.aligned.m8n8.x4.shared.b16 {%0,%1,%2,%3}, [%4];"
                       : "=r"(a0),"=r"(a1),"=r"(a2),"=r"(a3) : "r"(abase));
          #pragma unroll
          for (int ntv=0;ntv<8;ntv++){
            uint2 bv = *(const uint2*)&g_wfragd1[(tap*8+ntv)*64 + lane*2];
            asm volatile("mma.sync.aligned.m16n8k16.row.col.f32.bf16.bf16.f32 "
                         "{%0,%1,%2,%3}, {%4,%5,%6,%7}, {%8,%9}, {%0,%1,%2,%3};"
                         : "+f"(c[ntv][0]),"+f"(c[ntv][1]),"+f"(c[ntv][2]),"+f"(c[ntv][3])
                         : "r"(a0),"r"(a1),"r"(a2),"r"(a3),"r"(bv.x),"r"(bv.y));
          }
        }
      }
      int ho = 2*hb+ph;
      int wbA = wid*16+g, wbB = wbA+8;
      unsigned short* rb = g_d1h + ((size_t)(b*128+ho))*128*64;
      unsigned short* pA = rb + (size_t)(2*wbA+pw)*64 + 2*tig;
      unsigned short* pB = rb + (size_t)(2*wbB+pw)*64 + 2*tig;
      #pragma unroll
      for (int ntv=0;ntv<8;ntv++){
        *(u32*)(pA + ntv*8) = bfpack(fmaxf(c[ntv][0],0.f), fmaxf(c[ntv][1],0.f));
        *(u32*)(pB + ntv*8) = bfpack(fmaxf(c[ntv][2],0.f), fmaxf(c[ntv][3],0.f));
      }
    }
  }
}

// ------------- dec2: convT 64->32 via mma, 4 parities merged, B from global -
__global__ __launch_bounds__(128) void dec2m_k(const float* __restrict__ bias){
  constexpr int ROWB = 65*144;
  __shared__ __align__(16) unsigned char As[2*ROWB];
  __shared__ float bias_s[32];
  int tid = threadIdx.x, bx = blockIdx.x;
  int wchunk = bx & 1, hb = (bx>>1)&127, b = bx>>8;
  int wb0 = wchunk*64;
  if (tid<32) bias_s[tid]=bias[tid];
  for (int i=tid;i<2*65*8;i+=128){
    int r = i/520, rem = i%520, px = rem>>3, ch = rem&7;
    int hi = hb + r;
    int wi = wb0 + px;
    uint4 v = make_uint4(0,0,0,0);
    if (hi<128 && wi<128)
      v = *(const uint4*)&g_d1h[(((size_t)(b*128+hi))*128+wi)*64 + ch*8];
    *(uint4*)&As[r*ROWB + px*144 + ch*16] = v;
  }
  __syncthreads();
  u32 aSm = smem_u32(As);
  int lane = tid & 31, wid = tid>>5;
  int g = lane>>2, tig = lane&3;
  u32 laneRow = (u32)(lane & 15);
  u32 laneCol = (lane & 16) ? 16u : 0u;
  for (int ph=0; ph<2; ph++){
    for (int pw=0; pw<2; pw++){
      float c[4][4];
      #pragma unroll
      for (int ntv=0;ntv<4;ntv++){
        float bA = bias_s[ntv*8+2*tig], bB = bias_s[ntv*8+2*tig+1];
        c[ntv][0]=bA; c[ntv][1]=bB; c[ntv][2]=bA; c[ntv][3]=bB;
      }
      int nkh = ph?2:1, nkw = pw?2:1;
      for (int a=0;a<nkh;a++){
        int kh = ph ? a*2 : 1;
        int rtap = (ph && a==0) ? 1 : 0;
        for (int cc=0;cc<nkw;cc++){
          int kw = pw ? cc*2 : 1;
          int shift = (pw && cc==0) ? 1 : 0;
          int tap = kh*3+kw;
          u32 abase = aSm + rtap*ROWB + (wid*16 + shift + laneRow)*144 + laneCol;
          #pragma unroll
          for (int kt=0;kt<4;kt++){
            u32 a0,a1,a2,a3;
            asm volatile("ldmatrix.sync.aligned.m8n8.x4.shared.b16 {%0,%1,%2,%3}, [%4];"
                         : "=r"(a0),"=r"(a1),"=r"(a2),"=r"(a3)
                         : "r"(abase + kt*32));
            #pragma unroll
            for (int ntv=0;ntv<4;ntv++){
              uint2 bv = *(const uint2*)&g_wfrag[((tap*4+kt)*4+ntv)*64 + lane*2];
              asm volatile("mma.sync.aligned.m16n8k16.row.col.f32.bf16.bf16.f32 "
                           "{%0,%1,%2,%3}, {%4,%5,%6,%7}, {%8,%9}, {%0,%1,%2,%3};"
                           : "+f"(c[ntv][0]),"+f"(c[ntv][1]),"+f"(c[ntv][2]),"+f"(c[ntv][3])
                           : "r"(a0),"r"(a1),"r"(a2),"r"(a3),"r"(bv.x),"r"(bv.y));
            }
          }
        }
      }
      int ho = 2*hb+ph;
      int wbA = wb0 + wid*16 + g, wbB = wbA + 8;
      unsigned short* rowBase = g_d2h + ((size_t)(b*256+ho))*256*32;
      unsigned short* pA = rowBase + (size_t)(2*wbA+pw)*32 + 2*tig;
      unsigned short* pB = rowBase + (size_t)(2*wbB+pw)*32 + 2*tig;
      #pragma unroll
      for (int ntv=0;ntv<4;ntv++){
        *(u32*)(pA + ntv*8) = bfpack(fmaxf(c[ntv][0],0.f), fmaxf(c[ntv][1],0.f));
        *(u32*)(pB + ntv*8) = bfpack(fmaxf(c[ntv][2],0.f), fmaxf(c[ntv][3],0.f));
      }
    }
  }
}

// ------------- dec3: conv 32->3 via mma, 4 output rows/block + fused MSE ----
__global__ __launch_bounds__(128) void dec3_mma_k(const float* __restrict__ x,
                                                  const float* __restrict__ bias){
  constexpr int PXB = 80;
  __shared__ __align__(16) unsigned char As[6*66*PXB];   // 6 rows x 66 px
  __shared__ float bias_s[3];
  int tid = threadIdx.x, bx = blockIdx.x;
  int wchunk = bx & 3, hrow = (bx>>2)&63, b = bx>>8;
  int wb0 = wchunk*64;
  int ho0 = hrow*4;
  if (tid<3) bias_s[tid]=bias[tid];
  for (int i=tid;i<6*66*4;i+=128){
    int r=i/264, rem=i%264, px=rem>>2, q=rem&3;
    int hi=ho0-1+r, wi=wb0-1+px;
    uint4 v=make_uint4(0,0,0,0);
    if ((unsigned)hi<256u && (unsigned)wi<256u)
      v=*(const uint4*)&g_d2h[(((size_t)(b*256+hi))*256+wi)*32 + q*8];
    *(uint4*)&As[(r*66+px)*PXB + q*16]=v;
  }
  __syncthreads();
  u32 aSm=smem_u32(As);
  int lane=tid&31, wid=tid>>5;
  int g=lane>>2, tig=lane&3;
  u32 laneRow=(u32)(lane&15);
  u32 laneCol=(lane&16)?16u:0u;
  int co0 = 2*tig, co1 = co0+1;
  float ls = 0.f;
  for (int r=0;r<4;r++){
    float c[4]={0.f,0.f,0.f,0.f};
    #pragma unroll
    for (int kh=0;kh<3;kh++){
      #pragma unroll
      for (int kw=0;kw<3;kw++){
        int tap=kh*3+kw;
        u32 abase = aSm + (u32)((r+kh)*66 + wid*16 + kw + laneRow)*PXB + laneCol;
        #pragma unroll
        for (int kt=0;kt<2;kt++){
          u32 a0,a1,a2,a3;
          asm volatile("ldmatrix.sync.aligned.m8n8.x4.shared.b16 {%0,%1,%2,%3}, [%4];"
                       : "=r"(a0),"=r"(a1),"=r"(a2),"=r"(a3) : "r"(abase + kt*32));
          uint2 bv = *(const uint2*)&g_wfragd3[(tap*2+kt)*64 + lane*2];
          asm volatile("mma.sync.aligned.m16n8k16.row.col.f32.bf16.bf16.f32 "
                       "{%0,%1,%2,%3}, {%4,%5,%6,%7}, {%8,%9}, {%0,%1,%2,%3};"
                       : "+f"(c[0]),"+f"(c[1]),"+f"(c[2]),"+f"(c[3])
                       : "r"(a0),"r"(a1),"r"(a2),"r"(a3),"r"(bv.x),"r"(bv.y));
        }
      }
    }
    int ho = ho0 + r;
    int pxA = wb0 + wid*16 + g, pxB = pxA + 8;
    const float* xb = x + (size_t)b*3*65536 + ho*256;
    if (co0 < 3){
      float d0 = c[0] + bias_s[co0] - xb[(size_t)co0*65536 + pxA];
      float d1 = c[2] + bias_s[co0] - xb[(size_t)co0*65536 + pxB];
      ls = fmaf(d0,d0, fmaf(d1,d1, ls));
    }
    if (co1 < 3){
      float d0 = c[1] + bias_s[co1] - xb[(size_t)co1*65536 + pxA];
      float d1 = c[3] + bias_s[co1] - xb[(size_t)co1*65536 + pxB];
      ls = fmaf(d0,d0, fmaf(d1,d1, ls));
    }
  }
  float s = blockReduceSum(ls);
  if (tid==0) atomicAdd(&g_acc[1], (double)s);
}

// ------------- finalize -----------------------------------------------------
__global__ void final_k(float* __restrict__ out){
  double vq  = g_acc[0];
  double rec = g_acc[1];
  float e_q  = (float)(1.25 * vq / 4194304.0);
  float mse  = (float)(rec / 12582912.0);
  out[0] = e_q;
  out[1] = mse;
  out[2] = mse;
}

// ---------------- launch ----------------------------------------------------
extern "C" void kernel_launch(void* const* d_in, const int* in_sizes, int n_in,
                              void* d_out, int out_size){
  const float* x   = (const float*)d_in[0];
  const float* ew1 = (const float*)d_in[1];
  const float* eb1 = (const float*)d_in[2];
  const float* ew2 = (const float*)d_in[3];
  const float* eb2 = (const float*)d_in[4];
  const float* ew3 = (const float*)d_in[5];
  const float* eb3 = (const float*)d_in[6];
  const float* cb  = (const float*)d_in[7];
  const float* dw1 = (const float*)d_in[8];
  const float* db1 = (const float*)d_in[9];
  const float* dw2 = (const float*)d_in[10];
  const float* db2 = (const float*)d_in[11];
  const float* dw3 = (const float*)d_in[12];
  const float* db3 = (const float*)d_in[13];
  float* out = (float*)d_out;

  repack_k<<<64,256>>>(ew1, ew2, dw1, dw2, dw3, ew3, cb);
  enc1_mma_k<<<16384,128>>>(x, eb1);
  enc2_mma_k<<<4096,128>>>(eb2);
  vq_mma_k<<<4096,128>>>(cb, eb3);
  dec1m_k<<<4096,128>>>(db1);
  dec2m_k<<<16384,128>>>(db2);
  dec3_mma_k<<<16384,128>>>(x, db3);
  final_k<<<1,1>>>(out);
}

// round 16
// speedup vs baseline: 1.0640x; 1.0031x over previous
#include <cuda_runtime.h>
#include <cuda_bf16.h>
#include <cstdint>

typedef unsigned long long u64;
typedef unsigned int u32;

// ---------------- scratch (device globals; no allocations allowed) ----------
__device__ unsigned short g_b1h[(size_t)64*128*128*32];  // enc1 out NHWC bf16
__device__ unsigned short g_b2h[(size_t)64*64*64*64];    // enc2 out NHWC bf16
__device__ unsigned short g_qh[(size_t)64*64*64*16];     // quantized NHWC bf16
__device__ unsigned short g_d1h[(size_t)64*128*128*64];  // dec1 out NHWC bf16
__device__ unsigned short g_d2h[(size_t)64*256*256*32];  // dec2 out NHWC bf16

// B-frag tables, ALL pair-vectorized: two mma's worth of frags per 16B at lane*4
__device__ u32   g_wfrag1[512];     // enc1: [kt2][np2][lane32][sub2][reg2]
__device__ u32   g_wfrag2[18432];   // enc2: [tap9][kt2][np4][lane32][sub2][reg2]
__device__ u32   g_wfragd1[4608];   // dec1: [tap9][np4][lane32][sub2][reg2]
__device__ u32   g_wfrag[9216];     // dec2: [tap9][kt4][np2][lane32][sub2][reg2]
__device__ u32   g_wfragd3[1152];   // dec3: [tap9][lane32][kt2][reg2] (flip baked)
__device__ u32   g_wfragw3[512];    // enc3: [kt4][lane32][ntv2][reg2]
__device__ u32   g_wfragcb[4096];   // codebook: [cpair64][lane32][cs2][reg2]
__device__ float g_nrm[512];        // NEGATED half-norms, permuted [cpair32][tig4][j4]
__device__ double g_acc[2];         // [0]=vq sq-sum, [1]=recon sq-sum

// ---------------- helpers ----------------------------------------------------
__device__ __forceinline__ u32 bfpack(float lo, float hi){
  u32 r; asm("cvt.rn.bf16x2.f32 %0, %1, %2;" : "=r"(r) : "f"(hi), "f"(lo));
  return r;
}
__device__ __forceinline__ u32 smem_u32(const void* p){
  u32 a; asm("{ .reg .u64 t; cvta.to.shared.u64 t, %1; cvt.u32.u64 %0, t; }"
             : "=r"(a) : "l"(p));
  return a;
}
__device__ __forceinline__ float blockReduceSum(float v){
  __shared__ float red[32];
  #pragma unroll
  for (int o=16;o;o>>=1) v += __shfl_down_sync(0xffffffffu, v, o);
  int lane = threadIdx.x & 31, w = threadIdx.x >> 5;
  if (lane==0) red[w]=v;
  __syncthreads();
  if (w==0){
    v = (lane < ((int)blockDim.x>>5)) ? red[lane] : 0.f;
    #pragma unroll
    for (int o=16;o;o>>=1) v += __shfl_down_sync(0xffffffffu, v, o);
  }
  return v;
}
__device__ __forceinline__ unsigned short f2bf(float v){
  return __bfloat16_as_ushort(__float2bfloat16(v));
}

// ---------------- weight repack + accumulator reset -------------------------
__global__ void repack_k(const float* __restrict__ ew1, const float* __restrict__ ew2,
                         const float* __restrict__ dw1, const float* __restrict__ dw2,
                         const float* __restrict__ dw3, const float* __restrict__ w3,
                         const float* __restrict__ cb){
  int t = blockIdx.x*blockDim.x + threadIdx.x;
  int nt = gridDim.x*blockDim.x;
  if (blockIdx.x==0 && threadIdx.x<2) g_acc[threadIdx.x]=0.0;
  // enc1: idx = kt*256 + np*128 + lane*4 + sub*2 + reg
  for (int i=t;i<512;i+=nt){
    int reg=i&1; int sub=(i>>1)&1; int lane=(i>>2)&31; int np=(i>>7)&1; int kt=(i>>8)&1;
    int ntv = np*2+sub;
    int gg=lane>>2, tg=lane&3;
    int co = ntv*8+gg;
    int k0 = kt*16 + 2*tg + (reg?8:0);
    float w0=0.f, w1=0.f;
    if (k0<27){ int kh=k0/9, r=k0%9, kw=r/3, ci=r%3;
      w0 = ew1[((co*3+ci)*3+kh)*3+kw]; }
    if (k0+1<27){ int k1=k0+1; int kh=k1/9, r=k1%9, kw=r/3, ci=r%3;
      w1 = ew1[((co*3+ci)*3+kh)*3+kw]; }
    g_wfrag1[i] = (u32)f2bf(w0) | ((u32)f2bf(w1)<<16);
  }
  // enc2: idx = tap*1024 + kt*512 + np*128 + lane*4 + sub*2 + reg
  for (int i=t;i<18432;i+=nt){
    int reg=i&1; int sub=(i>>1)&1; int lane=(i>>2)&31; int np=(i>>7)&3; int kt=(i>>9)&1; int tap=i>>10;
    int ntv = np*2+sub;
    int kh=tap/3, kw=tap%3;
    int gg=lane>>2, tg=lane&3;
    int co = ntv*8+gg;
    int ci0 = kt*16 + 2*tg + (reg?8:0);
    g_wfrag2[i] = (u32)f2bf(ew2[((co*32+ci0)*3+kh)*3+kw])
                | ((u32)f2bf(ew2[((co*32+ci0+1)*3+kh)*3+kw])<<16);
  }
  // dec1: idx = tap*512 + np*128 + lane*4 + sub*2 + reg
  for (int i=t;i<4608;i+=nt){
    int reg=i&1; int sub=(i>>1)&1; int lane=(i>>2)&31; int np=(i>>7)&3; int tap=i>>9;
    int ntv = np*2+sub;
    int kh=tap/3, kw=tap%3;
    int gg=lane>>2, tg=lane&3;
    int co = ntv*8+gg;
    int ci0 = 2*tg + (reg?8:0);
    g_wfragd1[i] = (u32)f2bf(dw1[((ci0*64+co)*3+kh)*3+kw])
                 | ((u32)f2bf(dw1[(((ci0+1)*64+co)*3+kh)*3+kw])<<16);
  }
  // dec2: idx = (tap*4+kt)*256 + np*128 + lane*4 + sub*2 + reg
  for (int i=t;i<9216;i+=nt){
    int reg=i&1; int sub=(i>>1)&1; int lane=(i>>2)&31; int np=(i>>7)&1; int kt=(i>>8)&3; int tap=i>>10;
    int ntv = np*2+sub;
    int kh = tap/3, kw = tap%3;
    int gg = lane>>2, tg = lane&3;
    int co = ntv*8+gg;
    int ci0 = kt*16 + 2*tg + (reg?8:0);
    g_wfrag[i] = (u32)f2bf(dw2[((ci0*32+co)*3+kh)*3+kw])
               | ((u32)f2bf(dw2[(((ci0+1)*32+co)*3+kh)*3+kw])<<16);
  }
  // dec3: idx = tap*128 + lane*4 + kt*2 + reg (flip baked)
  for (int i=t;i<1152;i+=nt){
    int reg=i&1; int kt=(i>>1)&1; int lane=(i>>2)&31; int tap=i>>7;
    int kh=tap/3, kw=tap%3;
    int gg=lane>>2, tg=lane&3;
    int co=gg;
    int ci0 = kt*16 + 2*tg + (reg?8:0);
    float w0=0.f, w1=0.f;
    if (co<3){
      w0 = dw3[((ci0*3+co)*3+(2-kh))*3+(2-kw)];
      w1 = dw3[(((ci0+1)*3+co)*3+(2-kh))*3+(2-kw)];
    }
    g_wfragd3[i] = (u32)f2bf(w0) | ((u32)f2bf(w1)<<16);
  }
  // enc3 w3: idx = kt*128 + lane*4 + ntv*2 + reg
  for (int i=t;i<512;i+=nt){
    int reg=i&1; int ntv=(i>>1)&1; int lane=(i>>2)&31; int kt=i>>7;
    int gg=lane>>2, tg=lane&3;
    int d = ntv*8+gg;
    int ci0 = kt*16 + 2*tg + (reg?8:0);
    g_wfragw3[i] = (u32)f2bf(w3[d*64+ci0]) | ((u32)f2bf(w3[d*64+ci0+1])<<16);
  }
  // codebook: idx = cpair*128 + lane*4 + cs*2 + reg (chunk = 2*cpair+cs)
  for (int i=t;i<4096;i+=nt){
    int reg=i&1; int cs=(i>>1)&1; int lane=(i>>2)&31; int cpair=i>>7;
    int chunk = 2*cpair + cs;
    int gg=lane>>2, tg=lane&3;
    int cw = chunk*8+gg;
    int d0 = 2*tg + (reg?8:0);
    g_wfragcb[i] = (u32)f2bf(cb[cw*16+d0]) | ((u32)f2bf(cb[cw*16+d0+1])<<16);
  }
  // NEGATED half-norms, permuted for float4 loads:
  // g_nrm[cpair*16 + tig*4 + j], j in 0..3 -> chunk=2cp+(j>>1), k = chunk*8+2*tig+(j&1)
  for (int i=t;i<512;i+=nt){
    int j=i&3; int tig=(i>>2)&3; int cpair=i>>4;
    int chunk = 2*cpair + (j>>1);
    int k = chunk*8 + 2*tig + (j&1);
    float s=0.f;
    #pragma unroll
    for (int d=0;d<16;d++){ float e=cb[k*16+d]; s=fmaf(e,e,s); }
    g_nrm[i] = -0.5f*s;
  }
}

// ---------------- enc1: 3->32 via mma; im2col with smem offset table --------
__global__ __launch_bounds__(128) void enc1_mma_k(const float* __restrict__ x,
                                                  const float* __restrict__ bias){
  constexpr int PXB = 80;
  __shared__ __align__(16) unsigned char As[64*PXB];
  __shared__ float bias_s[32];
  __shared__ int offs[27], khs[27], kws[27];
  int tid = threadIdx.x, bx = blockIdx.x;
  int wchunk = bx & 1, ho = (bx>>1)&127, b = bx>>8;
  int wb0 = wchunk*64;
  if (tid<32) bias_s[tid]=bias[tid];
  if (tid<27){
    int kh=tid/9, r=tid%9, kw=r/3, ci=r%3;
    offs[tid] = ci*65536 + kh*256 + kw;
    khs[tid] = kh; kws[tid] = kw;
  }
  __syncthreads();
  const float* xb = x + (size_t)b*3*65536;
  int hbase = 2*ho-1, wbase = 2*wb0-1;
  int C = hbase*256 + wbase;
  for (int i=tid;i<2048;i+=128){
    int k=i>>6, px=i&63;
    unsigned short h=0;
    if (k<27){
      int hi = hbase + khs[k], wi = wbase + 2*px + kws[k];
      if ((unsigned)hi<256u && (unsigned)wi<256u)
        h = f2bf(xb[offs[k] + C + 2*px]);
    }
    *(unsigned short*)&As[px*PXB + k*2] = h;
  }
  __syncthreads();
  u32 aSm = smem_u32(As);
  int lane=tid&31, wid=tid>>5;
  int g=lane>>2, tig=lane&3;
  u32 laneRow=(u32)(lane&15), laneCol=(lane&16)?16u:0u;
  float c[4][4];
  #pragma unroll
  for (int ntv=0;ntv<4;ntv++){
    float bA=bias_s[ntv*8+2*tig], bB=bias_s[ntv*8+2*tig+1];
    c[ntv][0]=bA; c[ntv][1]=bB; c[ntv][2]=bA; c[ntv][3]=bB;
  }
  u32 abase = aSm + (u32)(wid*16+laneRow)*PXB + laneCol;
  #pragma unroll
  for (int kt=0;kt<2;kt++){
    u32 a0,a1,a2,a3;
    asm volatile("ldmatrix.sync.aligned.m8n8.x4.shared.b16 {%0,%1,%2,%3}, [%4];"
                 : "=r"(a0),"=r"(a1),"=r"(a2),"=r"(a3) : "r"(abase + kt*32));
    #pragma unroll
    for (int np=0;np<2;np++){
      uint4 bv = *(const uint4*)&g_wfrag1[kt*256 + np*128 + lane*4];
      asm volatile("mma.sync.aligned.m16n8k16.row.col.f32.bf16.bf16.f32 "
                   "{%0,%1,%2,%3}, {%4,%5,%6,%7}, {%8,%9}, {%0,%1,%2,%3};"
                   : "+f"(c[2*np][0]),"+f"(c[2*np][1]),"+f"(c[2*np][2]),"+f"(c[2*np][3])
                   : "r"(a0),"r"(a1),"r"(a2),"r"(a3),"r"(bv.x),"r"(bv.y));
      asm volatile("mma.sync.aligned.m16n8k16.row.col.f32.bf16.bf16.f32 "
                   "{%0,%1,%2,%3}, {%4,%5,%6,%7}, {%8,%9}, {%0,%1,%2,%3};"
                   : "+f"(c[2*np+1][0]),"+f"(c[2*np+1][1]),"+f"(c[2*np+1][2]),"+f"(c[2*np+1][3])
                   : "r"(a0),"r"(a1),"r"(a2),"r"(a3),"r"(bv.z),"r"(bv.w));
    }
  }
  int woA = wb0 + wid*16 + g, woB = woA + 8;
  unsigned short* rb = g_b1h + ((size_t)(b*128+ho))*128*32;
  unsigned short* pA = rb + (size_t)woA*32 + 2*tig;
  unsigned short* pB = rb + (size_t)woB*32 + 2*tig;
  #pragma unroll
  for (int ntv=0;ntv<4;ntv++){
    *(u32*)(pA + ntv*8) = bfpack(fmaxf(c[ntv][0],0.f), fmaxf(c[ntv][1],0.f));
    *(u32*)(pB + ntv*8) = bfpack(fmaxf(c[ntv][2],0.f), fmaxf(c[ntv][3],0.f));
  }
}

// ---------------- enc2: 32->64 k3 s2 p1 relu via mma bf16; bf16 out ---------
__global__ __launch_bounds__(128) void enc2_mma_k(const float* __restrict__ bias){
  constexpr int ROWB = 129*80;
  __shared__ __align__(16) unsigned char As[3*ROWB];
  __shared__ float bias_s[64];
  int tid = threadIdx.x, bx = blockIdx.x;
  int ho = bx & 63, b = bx >> 6;
  if (tid<64) bias_s[tid]=bias[tid];
  for (int i=tid;i<3*129*4;i+=128){
    int r=i/516, rem=i%516, px=rem>>2, ch=rem&3;
    int hi=2*ho-1+r, wi=px-1;
    uint4 v=make_uint4(0,0,0,0);
    if ((unsigned)hi<128u && (unsigned)wi<128u)
      v = *(const uint4*)&g_b1h[(((size_t)(b*128+hi))*128+wi)*32 + ch*8];
    *(uint4*)&As[r*ROWB + px*80 + ch*16] = v;
  }
  __syncthreads();
  u32 aSm = smem_u32(As);
  int lane = tid&31, wid = tid>>5;
  int g = lane>>2, tig = lane&3;
  float c[8][4];
  #pragma unroll
  for (int ntv=0;ntv<8;ntv++){
    float bA=bias_s[ntv*8+2*tig], bB=bias_s[ntv*8+2*tig+1];
    c[ntv][0]=bA; c[ntv][1]=bB; c[ntv][2]=bA; c[ntv][3]=bB;
  }
  u32 laneRow = (u32)(lane & 15);
  u32 laneCol = (lane & 16) ? 16u : 0u;
  #pragma unroll
  for (int kh=0;kh<3;kh++){
    #pragma unroll
    for (int kw=0;kw<3;kw++){
      int tap = kh*3+kw;
      #pragma unroll
      for (int kt=0;kt<2;kt++){
        u32 abase = aSm + kh*ROWB + (wid*32 + 2*laneRow + kw)*80 + kt*32 + laneCol;
        u32 a0,a1,a2,a3;
        asm volatile("ldmatrix.sync.aligned.m8n8.x4.shared.b16 {%0,%1,%2,%3}, [%4];"
                     : "=r"(a0),"=r"(a1),"=r"(a2),"=r"(a3) : "r"(abase));
        #pragma unroll
        for (int np=0;np<4;np++){
          uint4 bv = *(const uint4*)&g_wfrag2[tap*1024 + kt*512 + np*128 + lane*4];
          asm volatile("mma.sync.aligned.m16n8k16.row.col.f32.bf16.bf16.f32 "
                       "{%0,%1,%2,%3}, {%4,%5,%6,%7}, {%8,%9}, {%0,%1,%2,%3};"
                       : "+f"(c[2*np][0]),"+f"(c[2*np][1]),"+f"(c[2*np][2]),"+f"(c[2*np][3])
                       : "r"(a0),"r"(a1),"r"(a2),"r"(a3),"r"(bv.x),"r"(bv.y));
          asm volatile("mma.sync.aligned.m16n8k16.row.col.f32.bf16.bf16.f32 "
                       "{%0,%1,%2,%3}, {%4,%5,%6,%7}, {%8,%9}, {%0,%1,%2,%3};"
                       : "+f"(c[2*np+1][0]),"+f"(c[2*np+1][1]),"+f"(c[2*np+1][2]),"+f"(c[2*np+1][3])
                       : "r"(a0),"r"(a1),"r"(a2),"r"(a3),"r"(bv.z),"r"(bv.w));
        }
      }
    }
  }
  int woA = wid*16+g, woB = woA+8;
  unsigned short* base = g_b2h + ((size_t)(b*64+ho))*64*64;
  unsigned short* pA = base + (size_t)woA*64 + 2*tig;
  unsigned short* pB = base + (size_t)woB*64 + 2*tig;
  #pragma unroll
  for (int ntv=0;ntv<8;ntv++){
    *(u32*)(pA + ntv*8) = bfpack(fmaxf(c[ntv][0],0.f), fmaxf(c[ntv][1],0.f));
    *(u32*)(pB + ntv*8) = bfpack(fmaxf(c[ntv][2],0.f), fmaxf(c[ntv][3],0.f));
  }
}

// ------------- VQ via mma: z-GEMM + scoring GEMM + quantize + loss ----------
__global__ __launch_bounds__(128) void vq_mma_k(const float* __restrict__ cb,
                                                const float* __restrict__ b3){
  __shared__ __align__(16) unsigned char As[64*144];
  __shared__ __align__(16) u32 CBf[4096];
  __shared__ __align__(16) float nrm_s[512];
  int tid = threadIdx.x;
  size_t base = (size_t)blockIdx.x*64;
  for (int i=tid;i<4096;i+=128) CBf[i]=g_wfragcb[i];
  for (int i=tid;i<512;i+=128) nrm_s[i]=g_nrm[i];
  for (int i=tid;i<512;i+=128){
    int px=i>>3, ch=i&7;
    uint4 v = *(const uint4*)&g_b2h[(base+px)*64 + ch*8];
    *(uint4*)&As[px*144 + ch*16] = v;
  }
  __syncthreads();
  u32 aSm=smem_u32(As), cbSm=smem_u32(CBf), nrSm=smem_u32(nrm_s);
  int lane=tid&31, wid=tid>>5;
  int g=lane>>2, tig=lane&3;
  u32 laneRow=(u32)(lane&15), laneCol=(lane&16)?16u:0u;
  float zc[2][4];
  #pragma unroll
  for (int ntv=0;ntv<2;ntv++){
    float bA=b3[ntv*8+2*tig], bB=b3[ntv*8+2*tig+1];
    zc[ntv][0]=bA; zc[ntv][1]=bB; zc[ntv][2]=bA; zc[ntv][3]=bB;
  }
  u32 abase = aSm + (u32)(wid*16+laneRow)*144 + laneCol;
  #pragma unroll
  for (int kt=0;kt<4;kt++){
    u32 a0,a1,a2,a3;
    asm volatile("ldmatrix.sync.aligned.m8n8.x4.shared.b16 {%0,%1,%2,%3}, [%4];"
                 : "=r"(a0),"=r"(a1),"=r"(a2),"=r"(a3) : "r"(abase + kt*32));
    uint4 bv = *(const uint4*)&g_wfragw3[kt*128 + lane*4];
    asm volatile("mma.sync.aligned.m16n8k16.row.col.f32.bf16.bf16.f32 "
                 "{%0,%1,%2,%3}, {%4,%5,%6,%7}, {%8,%9}, {%0,%1,%2,%3};"
                 : "+f"(zc[0][0]),"+f"(zc[0][1]),"+f"(zc[0][2]),"+f"(zc[0][3])
                 : "r"(a0),"r"(a1),"r"(a2),"r"(a3),"r"(bv.x),"r"(bv.y));
    asm volatile("mma.sync.aligned.m16n8k16.row.col.f32.bf16.bf16.f32 "
                 "{%0,%1,%2,%3}, {%4,%5,%6,%7}, {%8,%9}, {%0,%1,%2,%3};"
                 : "+f"(zc[1][0]),"+f"(zc[1][1]),"+f"(zc[1][2]),"+f"(zc[1][3])
                 : "r"(a0),"r"(a1),"r"(a2),"r"(a3),"r"(bv.z),"r"(bv.w));
  }
  u32 aZ0=bfpack(zc[0][0],zc[0][1]);
  u32 aZ1=bfpack(zc[0][2],zc[0][3]);
  u32 aZ2=bfpack(zc[1][0],zc[1][1]);
  u32 aZ3=bfpack(zc[1][2],zc[1][3]);
  float best0=-3.4e38f, best1=-3.4e38f; int bi0=0, bi1=0;
  for (int cpair=0;cpair<32;cpair++){
    float4 nk; // pre-negated: {-nA0,-nA1,-nB0,-nB1}
    asm volatile("ld.shared.v4.f32 {%0,%1,%2,%3}, [%4];"
                 : "=f"(nk.x),"=f"(nk.y),"=f"(nk.z),"=f"(nk.w)
                 : "r"(nrSm + (cpair*16+tig*4)*4));
    uint4 bv;
    asm volatile("ld.shared.v4.u32 {%0,%1,%2,%3}, [%4];"
                 : "=r"(bv.x),"=r"(bv.y),"=r"(bv.z),"=r"(bv.w)
                 : "r"(cbSm + (cpair*128 + lane*4)*4));
    float s0=nk.x, s1=nk.y, s2=nk.x, s3=nk.y;
    asm volatile("mma.sync.aligned.m16n8k16.row.col.f32.bf16.bf16.f32 "
                 "{%0,%1,%2,%3}, {%4,%5,%6,%7}, {%8,%9}, {%0,%1,%2,%3};"
                 : "+f"(s0),"+f"(s1),"+f"(s2),"+f"(s3)
                 : "r"(aZ0),"r"(aZ1),"r"(aZ2),"r"(aZ3),"r"(bv.x),"r"(bv.y));
    float t0=nk.z, t1=nk.w, t2=nk.z, t3=nk.w;
    asm volatile("mma.sync.aligned.m16n8k16.row.col.f32.bf16.bf16.f32 "
                 "{%0,%1,%2,%3}, {%4,%5,%6,%7}, {%8,%9}, {%0,%1,%2,%3};"
                 : "+f"(t0),"+f"(t1),"+f"(t2),"+f"(t3)
                 : "r"(aZ0),"r"(aZ1),"r"(aZ2),"r"(aZ3),"r"(bv.z),"r"(bv.w));
    int i0 = cpair*16 + 2*tig;
    float cs; int ci;
    if (s1>s0){cs=s1;ci=i0+1;} else {cs=s0;ci=i0;}
    if (cs>best0){best0=cs;bi0=ci;}
    if (s3>s2){cs=s3;ci=i0+1;} else {cs=s2;ci=i0;}
    if (cs>best1){best1=cs;bi1=ci;}
    int i1 = i0 + 8;
    if (t1>t0){cs=t1;ci=i1+1;} else {cs=t0;ci=i1;}
    if (cs>best0){best0=cs;bi0=ci;}
    if (t3>t2){cs=t3;ci=i1+1;} else {cs=t2;ci=i1;}
    if (cs>best1){best1=cs;bi1=ci;}
  }
  #pragma unroll
  for (int off=1;off<4;off<<=1){
    float os=__shfl_xor_sync(0xffffffffu,best0,off);
    int   oi=__shfl_xor_sync(0xffffffffu,bi0,off);
    if (os>best0 || (os==best0 && oi<bi0)){best0=os;bi0=oi;}
    os=__shfl_xor_sync(0xffffffffu,best1,off);
    oi=__shfl_xor_sync(0xffffffffu,bi1,off);
    if (os>best1 || (os==best1 && oi<bi1)){best1=os;bi1=oi;}
  }
  size_t px0 = base + wid*16 + g, px1 = px0 + 8;
  float ls=0.f;
  {
    const float* e = cb + (size_t)bi0*16;
    *(u32*)&g_qh[px0*16 + tig*4]     = bfpack(e[tig*4],e[tig*4+1]);
    *(u32*)&g_qh[px0*16 + tig*4 + 2] = bfpack(e[tig*4+2],e[tig*4+3]);
    float d0=e[2*tig]-zc[0][0],   d1=e[2*tig+1]-zc[0][1];
    float d2=e[8+2*tig]-zc[1][0], d3=e[8+2*tig+1]-zc[1][1];
    ls = fmaf(d0,d0, fmaf(d1,d1, fmaf(d2,d2, fmaf(d3,d3, ls))));
  }
  {
    const float* e = cb + (size_t)bi1*16;
    *(u32*)&g_qh[px1*16 + tig*4]     = bfpack(e[tig*4],e[tig*4+1]);
    *(u32*)&g_qh[px1*16 + tig*4 + 2] = bfpack(e[tig*4+2],e[tig*4+3]);
    float d0=e[2*tig]-zc[0][2],   d1=e[2*tig+1]-zc[0][3];
    float d2=e[8+2*tig]-zc[1][2], d3=e[8+2*tig+1]-zc[1][3];
    ls = fmaf(d0,d0, fmaf(d1,d1, fmaf(d2,d2, fmaf(d3,d3, ls))));
  }
  float s = blockReduceSum(ls);
  if (tid==0) atomicAdd(&g_acc[0], (double)s);
}

// ------------- dec1: convT 16->64 via mma, 4 parities merged ----------------
__global__ __launch_bounds__(128) void dec1m_k(const float* __restrict__ bias){
  constexpr int ROWB = 65*48;
  __shared__ __align__(16) unsigned char As[2*ROWB];
  __shared__ float bias_s[64];
  int tid = threadIdx.x, bx = blockIdx.x;
  int hb = bx & 63, b = bx >> 6;
  if (tid<64) bias_s[tid]=bias[tid];
  for (int i=tid;i<2*65*2;i+=128){
    int r=i/130, rem=i%130, px=rem>>1, hf=rem&1;
    int hi=hb+r;
    uint4 v=make_uint4(0,0,0,0);
    if (hi<64 && px<64)
      v=*(const uint4*)&g_qh[(((size_t)(b*64+hi))*64+px)*16 + hf*8];
    *(uint4*)&As[r*ROWB+px*48+hf*16]=v;
  }
  __syncthreads();
  u32 aSm = smem_u32(As);
  int lane = tid&31, wid = tid>>5;
  int g = lane>>2, tig = lane&3;
  u32 laneRow = (u32)(lane & 15);
  u32 laneCol = (lane & 16) ? 16u : 0u;
  for (int ph=0; ph<2; ph++){
    for (int pw=0; pw<2; pw++){
      float c[8][4];
      #pragma unroll
      for (int ntv=0;ntv<8;ntv++){
        float bA=bias_s[ntv*8+2*tig], bB=bias_s[ntv*8+2*tig+1];
        c[ntv][0]=bA; c[ntv][1]=bB; c[ntv][2]=bA; c[ntv][3]=bB;
      }
      int nkh = ph?2:1, nkw = pw?2:1;
      for (int a=0;a<nkh;a++){
        int kh = ph ? a*2 : 1;
        int rtap = (ph && a==0) ? 1 : 0;
        for (int cc=0;cc<nkw;cc++){
          int kw = pw ? cc*2 : 1;
          int shift = (pw && cc==0) ? 1 : 0;
          int tap = kh*3+kw;
          u32 abase = aSm + rtap*ROWB + (wid*16 + shift + laneRow)*48 + laneCol;
          u32 a0,a1,a2,a3;
          asm volatile("ldmatrix.sync.aligned.m8n8.x4.shared.b16 {%0,%1,%2,%3}, [%4];"
                       : "=r"(a0),"=r"(a1),"=r"(a2),"=r"(a3) : "r"(abase));
          #pragma unroll
          for (int np=0;np<4;np++){
            uint4 bv = *(const uint4*)&g_wfragd1[tap*512 + np*128 + lane*4];
            asm volatile("mma.sync.aligned.m16n8k16.row.col.f32.bf16.bf16.f32 "
                         "{%0,%1,%2,%3}, {%4,%5,%6,%7}, {%8,%9}, {%0,%1,%2,%3};"
                         : "+f"(c[2*np][0]),"+f"(c[2*np][1]),"+f"(c[2*np][2]),"+f"(c[2*np][3])
                         : "r"(a0),"r"(a1),"r"(a2),"r"(a3),"r"(bv.x),"r"(bv.y));
            asm volatile("mma.sync.aligned.m16n8k16.row.col.f32.bf16.bf16.f32 "
                         "{%0,%1,%2,%3}, {%4,%5,%6,%7}, {%8,%9}, {%0,%1,%2,%3};"
                         : "+f"(c[2*np+1][0]),"+f"(c[2*np+1][1]),"+f"(c[2*np+1][2]),"+f"(c[2*np+1][3])
                         : "r"(a0),"r"(a1),"r"(a2),"r"(a3),"r"(bv.z),"r"(bv.w));
          }
        }
      }
      int ho = 2*hb+ph;
      int wbA = wid*16+g, wbB = wbA+8;
      unsigned short* rb = g_d1h + ((size_t)(b*128+ho))*128*64;
      unsigned short* pA = rb + (size_t)(2*wbA+pw)*64 + 2*tig;
      unsigned short* pB = rb + (size_t)(2*wbB+pw)*64 + 2*tig;
      #pragma unroll
      for (int ntv=0;ntv<8;ntv++){
        *(u32*)(pA + ntv*8) = bfpack(fmaxf(c[ntv][0],0.f), fmaxf(c[ntv][1],0.f));
        *(u32*)(pB + ntv*8) = bfpack(fmaxf(c[ntv][2],0.f), fmaxf(c[ntv][3],0.f));
      }
    }
  }
}

// ------------- dec2: convT 64->32 via mma, 4 parities merged ----------------
__global__ __launch_bounds__(128) void dec2m_k(const float* __restrict__ bias){
  constexpr int ROWB = 65*144;
  __shared__ __align__(16) unsigned char As[2*ROWB];
  __shared__ float bias_s[32];
  int tid = threadIdx.x, bx = blockIdx.x;
  int wchunk = bx & 1, hb = (bx>>1)&127, b = bx>>8;
  int wb0 = wchunk*64;
  if (tid<32) bias_s[tid]=bias[tid];
  for (int i=tid;i<2*65*8;i+=128){
    int r = i/520, rem = i%520, px = rem>>3, ch = rem&7;
    int hi = hb + r;
    int wi = wb0 + px;
    uint4 v = make_uint4(0,0,0,0);
    if (hi<128 && wi<128)
      v = *(const uint4*)&g_d1h[(((size_t)(b*128+hi))*128+wi)*64 + ch*8];
    *(uint4*)&As[r*ROWB + px*144 + ch*16] = v;
  }
  __syncthreads();
  u32 aSm = smem_u32(As);
  int lane = tid & 31, wid = tid>>5;
  int g = lane>>2, tig = lane&3;
  u32 laneRow = (u32)(lane & 15);
  u32 laneCol = (lane & 16) ? 16u : 0u;
  for (int ph=0; ph<2; ph++){
    for (int pw=0; pw<2; pw++){
      float c[4][4];
      #pragma unroll
      for (int ntv=0;ntv<4;ntv++){
        float bA = bias_s[ntv*8+2*tig], bB = bias_s[ntv*8+2*tig+1];
        c[ntv][0]=bA; c[ntv][1]=bB; c[ntv][2]=bA; c[ntv][3]=bB;
      }
      int nkh = ph?2:1, nkw = pw?2:1;
      for (int a=0;a<nkh;a++){
        int kh = ph ? a*2 : 1;
        int rtap = (ph && a==0) ? 1 : 0;
        for (int cc=0;cc<nkw;cc++){
          int kw = pw ? cc*2 : 1;
          int shift = (pw && cc==0) ? 1 : 0;
          int tap = kh*3+kw;
          u32 abase = aSm + rtap*ROWB + (wid*16 + shift + laneRow)*144 + laneCol;
          #pragma unroll
          for (int kt=0;kt<4;kt++){
            u32 a0,a1,a2,a3;
            asm volatile("ldmatrix.sync.aligned.m8n8.x4.shared.b16 {%0,%1,%2,%3}, [%4];"
                         : "=r"(a0),"=r"(a1),"=r"(a2),"=r"(a3)
                         : "r"(abase + kt*32));
            #pragma unroll
            for (int np=0;np<2;np++){
              uint4 bv = *(const uint4*)&g_wfrag[(tap*4+kt)*256 + np*128 + lane*4];
              asm volatile("mma.sync.aligned.m16n8k16.row.col.f32.bf16.bf16.f32 "
                           "{%0,%1,%2,%3}, {%4,%5,%6,%7}, {%8,%9}, {%0,%1,%2,%3};"
                           : "+f"(c[2*np][0]),"+f"(c[2*np][1]),"+f"(c[2*np][2]),"+f"(c[2*np][3])
                           : "r"(a0),"r"(a1),"r"(a2),"r"(a3),"r"(bv.x),"r"(bv.y));
              asm volatile("mma.sync.aligned.m16n8k16.row.col.f32.bf16.bf16.f32 "
                           "{%0,%1,%2,%3}, {%4,%5,%6,%7}, {%8,%9}, {%0,%1,%2,%3};"
                           : "+f"(c[2*np+1][0]),"+f"(c[2*np+1][1]),"+f"(c[2*np+1][2]),"+f"(c[2*np+1][3])
                           : "r"(a0),"r"(a1),"r"(a2),"r"(a3),"r"(bv.z),"r"(bv.w));
            }
          }
        }
      }
      int ho = 2*hb+ph;
      int wbA = wb0 + wid*16 + g, wbB = wbA + 8;
      unsigned short* rowBase = g_d2h + ((size_t)(b*256+ho))*256*32;
      unsigned short* pA = rowBase + (size_t)(2*wbA+pw)*32 + 2*tig;
      unsigned short* pB = rowBase + (size_t)(2*wbB+pw)*32 + 2*tig;
      #pragma unroll
      for (int ntv=0;ntv<4;ntv++){
        *(u32*)(pA + ntv*8) = bfpack(fmaxf(c[ntv][0],0.f), fmaxf(c[ntv][1],0.f));
        *(u32*)(pB + ntv*8) = bfpack(fmaxf(c[ntv][2],0.f), fmaxf(c[ntv][3],0.f));
      }
    }
  }
}

// ------------- dec3: conv 32->3 via mma, 4 output rows/block + fused MSE ----
__global__ __launch_bounds__(128) void dec3_mma_k(const float* __restrict__ x,
                                                  const float* __restrict__ bias){
  constexpr int PXB = 80;
  __shared__ __align__(16) unsigned char As[6*66*PXB];   // 6 rows x 66 px
  __shared__ float bias_s[3];
  int tid = threadIdx.x, bx = blockIdx.x;
  int wchunk = bx & 3, hrow = (bx>>2)&63, b = bx>>8;
  int wb0 = wchunk*64;
  int ho0 = hrow*4;
  if (tid<3) bias_s[tid]=bias[tid];
  for (int i=tid;i<6*66*4;i+=128){
    int r=i/264, rem=i%264, px=rem>>2, q=rem&3;
    int hi=ho0-1+r, wi=wb0-1+px;
    uint4 v=make_uint4(0,0,0,0);
    if ((unsigned)hi<256u && (unsigned)wi<256u)
      v=*(const uint4*)&g_d2h[(((size_t)(b*256+hi))*256+wi)*32 + q*8];
    *(uint4*)&As[(r*66+px)*PXB + q*16]=v;
  }
  __syncthreads();
  u32 aSm=smem_u32(As);
  int lane=tid&31, wid=tid>>5;
  int g=lane>>2, tig=lane&3;
  u32 laneRow=(u32)(lane&15);
  u32 laneCol=(lane&16)?16u:0u;
  int co0 = 2*tig, co1 = co0+1;
  float ls = 0.f;
  for (int r=0;r<4;r++){
    float c[4]={0.f,0.f,0.f,0.f};
    #pragma unroll
    for (int kh=0;kh<3;kh++){
      #pragma unroll
      for (int kw=0;kw<3;kw++){
        int tap=kh*3+kw;
        u32 abase = aSm + (u32)((r+kh)*66 + wid*16 + kw + laneRow)*PXB + laneCol;
        uint4 bv = *(const uint4*)&g_wfragd3[tap*128 + lane*4];
        u32 a0,a1,a2,a3;
        asm volatile("ldmatrix.sync.aligned.m8n8.x4.shared.b16 {%0,%1,%2,%3}, [%4];"
                     : "=r"(a0),"=r"(a1),"=r"(a2),"=r"(a3) : "r"(abase));
        asm volatile("mma.sync.aligned.m16n8k16.row.col.f32.bf16.bf16.f32 "
                     "{%0,%1,%2,%3}, {%4,%5,%6,%7}, {%8,%9}, {%0,%1,%2,%3};"
                     : "+f"(c[0]),"+f"(c[1]),"+f"(c[2]),"+f"(c[3])
                     : "r"(a0),"r"(a1),"r"(a2),"r"(a3),"r"(bv.x),"r"(bv.y));
        asm volatile("ldmatrix.sync.aligned.m8n8.x4.shared.b16 {%0,%1,%2,%3}, [%4];"
                     : "=r"(a0),"=r"(a1),"=r"(a2),"=r"(a3) : "r"(abase + 32));
        asm volatile("mma.sync.aligned.m16n8k16.row.col.f32.bf16.bf16.f32 "
                     "{%0,%1,%2,%3}, {%4,%5,%6,%7}, {%8,%9}, {%0,%1,%2,%3};"
                     : "+f"(c[0]),"+f"(c[1]),"+f"(c[2]),"+f"(c[3])
                     : "r"(a0),"r"(a1),"r"(a2),"r"(a3),"r"(bv.z),"r"(bv.w));
      }
    }
    int ho = ho0 + r;
    int pxA = wb0 + wid*16 + g, pxB = pxA + 8;
    const float* xb = x + (size_t)b*3*65536 + ho*256;
    if (co0 < 3){
      float d0 = c[0] + bias_s[co0] - xb[(size_t)co0*65536 + pxA];
      float d1 = c[2] + bias_s[co0] - xb[(size_t)co0*65536 + pxB];
      ls = fmaf(d0,d0, fmaf(d1,d1, ls));
    }
    if (co1 < 3){
      float d0 = c[1] + bias_s[co1] - xb[(size_t)co1*65536 + pxA];
      float d1 = c[3] + bias_s[co1] - xb[(size_t)co1*65536 + pxB];
      ls = fmaf(d0,d0, fmaf(d1,d1, ls));
    }
  }
  float s = blockReduceSum(ls);
  if (tid==0) atomicAdd(&g_acc[1], (double)s);
}

// ------------- finalize -----------------------------------------------------
__global__ void final_k(float* __restrict__ out){
  double vq  = g_acc[0];
  double rec = g_acc[1];
  float e_q  = (float)(1.25 * vq / 4194304.0);
  float mse  = (float)(rec / 12582912.0);
  out[0] = e_q;
  out[1] = mse;
  out[2] = mse;
}

// ---------------- launch ----------------------------------------------------
extern "C" void kernel_launch(void* const* d_in, const int* in_sizes, int n_in,
                              void* d_out, int out_size){
  const float* x   = (const float*)d_in[0];
  const float* ew1 = (const float*)d_in[1];
  const float* eb1 = (const float*)d_in[2];
  const float* ew2 = (const float*)d_in[3];
  const float* eb2 = (const float*)d_in[4];
  const float* ew3 = (const float*)d_in[5];
  const float* eb3 = (const float*)d_in[6];
  const float* cb  = (const float*)d_in[7];
  const float* dw1 = (const float*)d_in[8];
  const float* db1 = (const float*)d_in[9];
  const float* dw2 = (const float*)d_in[10];
  const float* db2 = (const float*)d_in[11];
  const float* dw3 = (const float*)d_in[12];
  const float* db3 = (const float*)d_in[13];
  float* out = (float*)d_out;

  repack_k<<<64,256>>>(ew1, ew2, dw1, dw2, dw3, ew3, cb);
  enc1_mma_k<<<16384,128>>>(x, eb1);
  enc2_mma_k<<<4096,128>>>(eb2);
  vq_mma_k<<<4096,128>>>(cb, eb3);
  dec1m_k<<<4096,128>>>(db1);
  dec2m_k<<<16384,128>>>(db2);
  dec3_mma_k<<<16384,128>>>(x, db3);
  final_k<<<1,1>>>(out);
}